// round 1
// baseline (speedup 1.0000x reference)
#include <cuda_runtime.h>
#include <math.h>

#define DIM    1024
#define HEADS  16
#define HD     64
#define WIN    16
#define NTOK   16384   // B*S = 2*8192
#define NWIN   1024    // NTOK / WIN

// Scratch (allocation-free rule: __device__ globals)
__device__ float g_q[NTOK * DIM];
__device__ float g_k[NTOK * DIM];
__device__ float g_v[NTOK * DIM];
__device__ float g_attn[NTOK * DIM];

// ---------------------------------------------------------------------------
// SGEMM: C[M,N] = A[M,K] * B[N,K]^T   (M=NTOK, N=K=DIM, all row-major)
// 128x128 block tile, BK=16, 256 threads, 8x8 register tile per thread.
// ---------------------------------------------------------------------------
constexpr int BM = 128, BN = 128, BK = 16, TM = 8, TN = 8;

__global__ __launch_bounds__(256, 2)
void sgemm_abt(const float* __restrict__ A, const float* __restrict__ B,
               float* __restrict__ C)
{
    __shared__ float As[BK][BM + 4];
    __shared__ float Bs[BK][BN + 4];

    const int tid = threadIdx.x;
    const int bm  = blockIdx.y * BM;
    const int bn  = blockIdx.x * BN;
    const int tr  = (tid / 16) * TM;     // 0..120
    const int tc  = (tid % 16) * TN;     // 0..120

    // load mapping: 128 rows x 16 cols per tile = 512 float4; 2 per thread
    const int lr = tid >> 2;             // 0..63
    const int lc = (tid & 3) * 4;        // 0,4,8,12

    const float* Ag = A + (long)bm * DIM;
    const float* Bg = B + (long)bn * DIM;

    float acc[TM][TN] = {};

    for (int k0 = 0; k0 < DIM; k0 += BK) {
        float4 a0 = *(const float4*)(Ag + (long)(lr)      * DIM + k0 + lc);
        float4 a1 = *(const float4*)(Ag + (long)(lr + 64) * DIM + k0 + lc);
        float4 b0 = *(const float4*)(Bg + (long)(lr)      * DIM + k0 + lc);
        float4 b1 = *(const float4*)(Bg + (long)(lr + 64) * DIM + k0 + lc);

        __syncthreads();   // previous tile fully consumed

        As[lc + 0][lr]      = a0.x; As[lc + 1][lr]      = a0.y;
        As[lc + 2][lr]      = a0.z; As[lc + 3][lr]      = a0.w;
        As[lc + 0][lr + 64] = a1.x; As[lc + 1][lr + 64] = a1.y;
        As[lc + 2][lr + 64] = a1.z; As[lc + 3][lr + 64] = a1.w;

        Bs[lc + 0][lr]      = b0.x; Bs[lc + 1][lr]      = b0.y;
        Bs[lc + 2][lr]      = b0.z; Bs[lc + 3][lr]      = b0.w;
        Bs[lc + 0][lr + 64] = b1.x; Bs[lc + 1][lr + 64] = b1.y;
        Bs[lc + 2][lr + 64] = b1.z; Bs[lc + 3][lr + 64] = b1.w;

        __syncthreads();

        #pragma unroll
        for (int kk = 0; kk < BK; kk++) {
            float ar[TM], br[TN];
            float4 t;
            t = *(const float4*)&As[kk][tr];     ar[0]=t.x; ar[1]=t.y; ar[2]=t.z; ar[3]=t.w;
            t = *(const float4*)&As[kk][tr + 4]; ar[4]=t.x; ar[5]=t.y; ar[6]=t.z; ar[7]=t.w;
            t = *(const float4*)&Bs[kk][tc];     br[0]=t.x; br[1]=t.y; br[2]=t.z; br[3]=t.w;
            t = *(const float4*)&Bs[kk][tc + 4]; br[4]=t.x; br[5]=t.y; br[6]=t.z; br[7]=t.w;
            #pragma unroll
            for (int i = 0; i < TM; i++)
                #pragma unroll
                for (int j = 0; j < TN; j++)
                    acc[i][j] = fmaf(ar[i], br[j], acc[i][j]);
        }
    }

    #pragma unroll
    for (int i = 0; i < TM; i++) {
        #pragma unroll
        for (int j = 0; j < TN; j += 4) {
            float4 o = make_float4(acc[i][j], acc[i][j+1], acc[i][j+2], acc[i][j+3]);
            *(float4*)(C + (long)(bm + tr + i) * DIM + bn + tc + j) = o;
        }
    }
}

// ---------------------------------------------------------------------------
// Windowed attention with fused RoPE.
// One block per window (1024 blocks), 256 threads.
// Per head: stage q(rope),k(rope),v into smem; scores->softmax->PV.
// ---------------------------------------------------------------------------
__global__ __launch_bounds__(256)
void attn_kernel(const float* __restrict__ rope)
{
    __shared__ float cs[WIN][HD / 2];
    __shared__ float sn[WIN][HD / 2];
    __shared__ float sq[WIN][HD + 1];
    __shared__ float sk[WIN][HD + 1];
    __shared__ float sv[WIN][HD];
    __shared__ float sp[WIN][WIN + 1];

    const int w = blockIdx.x;
    const int t = threadIdx.x;

    // cos/sin table: positions 0..15, 32 freqs each (rope_freqs row stride = 32)
    for (int e = t; e < WIN * (HD / 2); e += 256) {
        int r = e / (HD / 2), j = e % (HD / 2);
        sincosf(rope[r * (HD / 2) + j], &sn[r][j], &cs[r][j]);
    }
    __syncthreads();

    const int r = t >> 4;   // query row / stage row (0..15)
    const int c = t & 15;   // key col / lane within row group

    for (int h = 0; h < HEADS; h++) {
        const long base = ((long)w * WIN + r) * DIM + h * HD;

        // stage q,k (with split-half RoPE) and v
        {
            const int d0 = c * 4;
            #pragma unroll
            for (int dd = 0; dd < 4; dd++) {
                const int d = d0 + dd;
                float qv, kv;
                if (d < HD / 2) {
                    float q1 = g_q[base + d], q2 = g_q[base + d + HD / 2];
                    float k1 = g_k[base + d], k2 = g_k[base + d + HD / 2];
                    qv = q1 * cs[r][d] - q2 * sn[r][d];
                    kv = k1 * cs[r][d] - k2 * sn[r][d];
                } else {
                    int j = d - HD / 2;
                    float q1 = g_q[base + j], q2 = g_q[base + d];
                    float k1 = g_k[base + j], k2 = g_k[base + d];
                    qv = q1 * sn[r][j] + q2 * cs[r][j];
                    kv = k1 * sn[r][j] + k2 * cs[r][j];
                }
                sq[r][d] = qv;
                sk[r][d] = kv;
            }
            float4 vv = *(const float4*)(g_v + base + d0);
            *(float4*)&sv[r][d0] = vv;
        }
        __syncthreads();

        // scores: thread (r,c) -> s[r][c]
        float s = 0.f;
        #pragma unroll
        for (int d = 0; d < HD; d++)
            s = fmaf(sq[r][d], sk[c][d], s);
        s *= 0.125f;   // 1/sqrt(64)

        // row softmax over 16 lanes (lanes of a row are contiguous in the warp)
        float m = s;
        #pragma unroll
        for (int o = 8; o; o >>= 1)
            m = fmaxf(m, __shfl_xor_sync(0xffffffffu, m, o));
        float e = expf(s - m);
        float sum = e;
        #pragma unroll
        for (int o = 8; o; o >>= 1)
            sum += __shfl_xor_sync(0xffffffffu, sum, o);
        sp[r][c] = e / sum;
        __syncwarp();

        // PV: thread (r,c) computes out[r][c + 16*j], j=0..3
        #pragma unroll
        for (int j = 0; j < 4; j++) {
            const int d = c + 16 * j;
            float a = 0.f;
            #pragma unroll
            for (int kk = 0; kk < WIN; kk++)
                a = fmaf(sp[r][kk], sv[kk][d], a);
            g_attn[base + d] = a;
        }
        __syncthreads();   // before next head overwrites smem
    }
}

// ---------------------------------------------------------------------------
extern "C" void kernel_launch(void* const* d_in, const int* in_sizes, int n_in,
                              void* d_out, int out_size)
{
    const float* x    = (const float*)d_in[0];
    const float* rope = (const float*)d_in[1];
    const float* wq   = (const float*)d_in[2];
    const float* wk   = (const float*)d_in[3];
    const float* wv   = (const float*)d_in[4];
    const float* wo   = (const float*)d_in[5];
    float* out        = (float*)d_out;

    float *q, *k, *v, *attn;
    cudaGetSymbolAddress((void**)&q,    g_q);
    cudaGetSymbolAddress((void**)&k,    g_k);
    cudaGetSymbolAddress((void**)&v,    g_v);
    cudaGetSymbolAddress((void**)&attn, g_attn);

    dim3 gemm_grid(DIM / BN, NTOK / BM);   // (8, 128)
    sgemm_abt<<<gemm_grid, 256>>>(x, wq, q);
    sgemm_abt<<<gemm_grid, 256>>>(x, wk, k);
    sgemm_abt<<<gemm_grid, 256>>>(x, wv, v);

    attn_kernel<<<NWIN, 256>>>(rope);

    sgemm_abt<<<gemm_grid, 256>>>(attn, wo, out);
}

// round 3
// speedup vs baseline: 2.3145x; 2.3145x over previous
#include <cuda_runtime.h>
#include <cstdint>
#include <math.h>

#define DIM    1024
#define HEADS  16
#define HD     64
#define WIN    16
#define NTOK   16384   // B*S
#define NWIN   1024

// Scratch (allocation-free rule: __device__ globals)
__device__ __align__(16) float g_q[NTOK * DIM];
__device__ __align__(16) float g_k[NTOK * DIM];
__device__ __align__(16) float g_v[NTOK * DIM];
__device__ __align__(16) float g_attn[NTOK * DIM];

__device__ __forceinline__ uint32_t f2tf32(float f) {
    uint32_t r;
    asm("cvt.rna.tf32.f32 %0, %1;" : "=r"(r) : "f"(f));
    return r;
}

__device__ __forceinline__ void mma_tf32_16x8x8(float c[4],
                                                uint32_t a0, uint32_t a1,
                                                uint32_t a2, uint32_t a3,
                                                uint32_t b0, uint32_t b1) {
    asm volatile(
        "mma.sync.aligned.m16n8k8.row.col.f32.tf32.tf32.f32 "
        "{%0,%1,%2,%3}, {%4,%5,%6,%7}, {%8,%9}, {%0,%1,%2,%3};"
        : "+f"(c[0]), "+f"(c[1]), "+f"(c[2]), "+f"(c[3])
        : "r"(a0), "r"(a1), "r"(a2), "r"(a3), "r"(b0), "r"(b1));
}

// ---------------------------------------------------------------------------
// tf32 mma.sync GEMM: C[M,N] = A[M,K] * B[N,K]^T ; M=16384, N=K=1024
// CTA tile 128x128, BK=32, 256 threads (8 warps, each 64x32).
// Smem layout [m][k] with row stride 36 words -> conflict-free fragment LDS.
// ---------------------------------------------------------------------------
constexpr int BM = 128, BN = 128, BK = 32;
constexpr int SSTRIDE = 36;                       // words per smem row
constexpr int TILE_WORDS = 128 * SSTRIDE;         // 4608 words = 18432 B
// smem: [A0][B0][A1][B1]
#define SMEM_WORDS (4 * TILE_WORDS)               // 73728 B

__global__ __launch_bounds__(256, 2)
void gemm_tf32(const float4* __restrict__ A, const float4* __restrict__ B,
               float* __restrict__ C)
{
    extern __shared__ uint32_t smem[];
    uint32_t* sA[2] = { smem,                 smem + 2 * TILE_WORDS };
    uint32_t* sB[2] = { smem + TILE_WORDS,    smem + 3 * TILE_WORDS };

    const int tid = threadIdx.x;
    const int wid = tid >> 5, lane = tid & 31;
    const int g    = lane >> 2;       // group row 0..7
    const int tid4 = lane & 3;        // 0..3
    const int warpM = wid >> 2;       // 0..1 -> 64 rows
    const int warpN = wid & 3;        // 0..3 -> 32 cols
    const int bm = blockIdx.y * BM, bn = blockIdx.x * BN;

    // global load mapping: 1024 float4 per tile, 4 per thread
    const int row0 = tid >> 3;        // 0..31
    const int c4   = tid & 7;         // 0..7 (k float4 group)

    const float4* Ag = A + (size_t)(bm + row0) * (DIM / 4) + c4;
    const float4* Bg = B + (size_t)(bn + row0) * (DIM / 4) + c4;

    float acc[4][4][4];
    #pragma unroll
    for (int i = 0; i < 4; i++)
        #pragma unroll
        for (int j = 0; j < 4; j++)
            #pragma unroll
            for (int q = 0; q < 4; q++)
                acc[i][j][q] = 0.f;

    float4 ra[4], rb[4];

    auto ldg_tile = [&](int kt) {
        const size_t ko = (size_t)kt * (BK / 4);
        #pragma unroll
        for (int i = 0; i < 4; i++) {
            ra[i] = Ag[ko + (size_t)(32 * i) * (DIM / 4)];
            rb[i] = Bg[ko + (size_t)(32 * i) * (DIM / 4)];
        }
    };
    auto sts_tile = [&](int b) {
        #pragma unroll
        for (int i = 0; i < 4; i++) {
            uint4 ta = { f2tf32(ra[i].x), f2tf32(ra[i].y), f2tf32(ra[i].z), f2tf32(ra[i].w) };
            uint4 tb = { f2tf32(rb[i].x), f2tf32(rb[i].y), f2tf32(rb[i].z), f2tf32(rb[i].w) };
            *reinterpret_cast<uint4*>(sA[b] + (row0 + 32 * i) * SSTRIDE + 4 * c4) = ta;
            *reinterpret_cast<uint4*>(sB[b] + (row0 + 32 * i) * SSTRIDE + 4 * c4) = tb;
        }
    };

    ldg_tile(0);
    sts_tile(0);
    __syncthreads();

    const int NKT = DIM / BK;   // 32
    for (int kt = 0; kt < NKT; kt++) {
        const int b = kt & 1;
        if (kt + 1 < NKT) ldg_tile(kt + 1);

        const uint32_t* Aw = sA[b] + (warpM * 64 + g) * SSTRIDE;
        const uint32_t* Bw = sB[b] + (warpN * 32 + g) * SSTRIDE;

        #pragma unroll
        for (int kk = 0; kk < 4; kk++) {
            const int kidx = kk * 8 + tid4;
            uint32_t af[4][4], bf[4][2];
            #pragma unroll
            for (int mt = 0; mt < 4; mt++) {
                af[mt][0] = Aw[(mt * 16)     * SSTRIDE + kidx];
                af[mt][1] = Aw[(mt * 16 + 8) * SSTRIDE + kidx];
                af[mt][2] = Aw[(mt * 16)     * SSTRIDE + kidx + 4];
                af[mt][3] = Aw[(mt * 16 + 8) * SSTRIDE + kidx + 4];
            }
            #pragma unroll
            for (int nt = 0; nt < 4; nt++) {
                bf[nt][0] = Bw[(nt * 8) * SSTRIDE + kidx];
                bf[nt][1] = Bw[(nt * 8) * SSTRIDE + kidx + 4];
            }
            #pragma unroll
            for (int mt = 0; mt < 4; mt++)
                #pragma unroll
                for (int nt = 0; nt < 4; nt++)
                    mma_tf32_16x8x8(acc[mt][nt],
                                    af[mt][0], af[mt][1], af[mt][2], af[mt][3],
                                    bf[nt][0], bf[nt][1]);
        }

        if (kt + 1 < NKT) {
            __syncthreads();        // everyone done reading buf b^1 (iter kt-1)
            sts_tile(b ^ 1);
            __syncthreads();
        }
    }

    // epilogue
    #pragma unroll
    for (int mt = 0; mt < 4; mt++) {
        const int r0 = bm + warpM * 64 + mt * 16 + g;
        #pragma unroll
        for (int nt = 0; nt < 4; nt++) {
            const int col = bn + warpN * 32 + nt * 8 + 2 * tid4;
            float2 v0 = make_float2(acc[mt][nt][0], acc[mt][nt][1]);
            float2 v1 = make_float2(acc[mt][nt][2], acc[mt][nt][3]);
            *(float2*)(C + (size_t)r0 * DIM + col)       = v0;
            *(float2*)(C + (size_t)(r0 + 8) * DIM + col) = v1;
        }
    }
}

// ---------------------------------------------------------------------------
// Windowed attention with fused RoPE (unchanged from R1).
// ---------------------------------------------------------------------------
__global__ __launch_bounds__(256)
void attn_kernel(const float* __restrict__ rope)
{
    __shared__ float cs[WIN][HD / 2];
    __shared__ float sn[WIN][HD / 2];
    __shared__ float sq[WIN][HD + 1];
    __shared__ float sk[WIN][HD + 1];
    __shared__ float sv[WIN][HD];
    __shared__ float sp[WIN][WIN + 1];

    const int w = blockIdx.x;
    const int t = threadIdx.x;

    for (int e = t; e < WIN * (HD / 2); e += 256) {
        int r = e / (HD / 2), j = e % (HD / 2);
        sincosf(rope[r * (HD / 2) + j], &sn[r][j], &cs[r][j]);
    }
    __syncthreads();

    const int r = t >> 4;
    const int c = t & 15;

    for (int h = 0; h < HEADS; h++) {
        const long base = ((long)w * WIN + r) * DIM + h * HD;
        {
            const int d0 = c * 4;
            #pragma unroll
            for (int dd = 0; dd < 4; dd++) {
                const int d = d0 + dd;
                float qv, kv;
                if (d < HD / 2) {
                    float q1 = g_q[base + d], q2 = g_q[base + d + HD / 2];
                    float k1 = g_k[base + d], k2 = g_k[base + d + HD / 2];
                    qv = q1 * cs[r][d] - q2 * sn[r][d];
                    kv = k1 * cs[r][d] - k2 * sn[r][d];
                } else {
                    int j = d - HD / 2;
                    float q1 = g_q[base + j], q2 = g_q[base + d];
                    float k1 = g_k[base + j], k2 = g_k[base + d];
                    qv = q1 * sn[r][j] + q2 * cs[r][j];
                    kv = k1 * sn[r][j] + k2 * cs[r][j];
                }
                sq[r][d] = qv;
                sk[r][d] = kv;
            }
            float4 vv = *(const float4*)(g_v + base + d0);
            *(float4*)&sv[r][d0] = vv;
        }
        __syncthreads();

        float s = 0.f;
        #pragma unroll
        for (int d = 0; d < HD; d++)
            s = fmaf(sq[r][d], sk[c][d], s);
        s *= 0.125f;

        float m = s;
        #pragma unroll
        for (int o = 8; o; o >>= 1)
            m = fmaxf(m, __shfl_xor_sync(0xffffffffu, m, o));
        float e = expf(s - m);
        float sum = e;
        #pragma unroll
        for (int o = 8; o; o >>= 1)
            sum += __shfl_xor_sync(0xffffffffu, sum, o);
        sp[r][c] = e / sum;
        __syncwarp();

        #pragma unroll
        for (int j = 0; j < 4; j++) {
            const int d = c + 16 * j;
            float a = 0.f;
            #pragma unroll
            for (int kk = 0; kk < WIN; kk++)
                a = fmaf(sp[r][kk], sv[kk][d], a);
            g_attn[base + d] = a;
        }
        __syncthreads();
    }
}

// ---------------------------------------------------------------------------
extern "C" void kernel_launch(void* const* d_in, const int* in_sizes, int n_in,
                              void* d_out, int out_size)
{
    const float* x    = (const float*)d_in[0];
    const float* rope = (const float*)d_in[1];
    const float* wq   = (const float*)d_in[2];
    const float* wk   = (const float*)d_in[3];
    const float* wv   = (const float*)d_in[4];
    const float* wo   = (const float*)d_in[5];
    float* out        = (float*)d_out;

    float *q, *k, *v, *attn;
    cudaGetSymbolAddress((void**)&q,    g_q);
    cudaGetSymbolAddress((void**)&k,    g_k);
    cudaGetSymbolAddress((void**)&v,    g_v);
    cudaGetSymbolAddress((void**)&attn, g_attn);

    cudaFuncSetAttribute(gemm_tf32, cudaFuncAttributeMaxDynamicSharedMemorySize,
                         SMEM_WORDS * 4);

    dim3 grid(DIM / BN, NTOK / BM);   // (8, 128)
    size_t shmem = SMEM_WORDS * 4;
    gemm_tf32<<<grid, 256, shmem>>>((const float4*)x, (const float4*)wq, q);
    gemm_tf32<<<grid, 256, shmem>>>((const float4*)x, (const float4*)wk, k);
    gemm_tf32<<<grid, 256, shmem>>>((const float4*)x, (const float4*)wv, v);

    attn_kernel<<<NWIN, 256>>>(rope);

    gemm_tf32<<<grid, 256, shmem>>>((const float4*)attn, (const float4*)wo, out);
}

// round 4
// speedup vs baseline: 2.7513x; 1.1887x over previous
#include <cuda_runtime.h>
#include <cstdint>
#include <math.h>

#define DIM    1024
#define HEADS  16
#define HD     64
#define WIN    16
#define NTOK   16384   // B*S
#define NWIN   1024

// Scratch (allocation-free rule: __device__ globals)
__device__ __align__(16) float g_q[NTOK * DIM];
__device__ __align__(16) float g_k[NTOK * DIM];
__device__ __align__(16) float g_v[NTOK * DIM];
__device__ __align__(16) float g_attn[NTOK * DIM];

__device__ __forceinline__ uint32_t f2tf32(float f) {
    uint32_t r;
    asm("cvt.rna.tf32.f32 %0, %1;" : "=r"(r) : "f"(f));
    return r;
}

__device__ __forceinline__ void mma_tf32_16x8x8(float c[4],
                                                uint32_t a0, uint32_t a1,
                                                uint32_t a2, uint32_t a3,
                                                uint32_t b0, uint32_t b1) {
    asm volatile(
        "mma.sync.aligned.m16n8k8.row.col.f32.tf32.tf32.f32 "
        "{%0,%1,%2,%3}, {%4,%5,%6,%7}, {%8,%9}, {%0,%1,%2,%3};"
        : "+f"(c[0]), "+f"(c[1]), "+f"(c[2]), "+f"(c[3])
        : "r"(a0), "r"(a1), "r"(a2), "r"(a3), "r"(b0), "r"(b1));
}

// ---------------------------------------------------------------------------
// tf32 mma.sync GEMM: C[M,N] = A[M,K] * B[N,K]^T ; M=16384, N=K=1024
// CTA tile 128x128, BK=32, 256 threads (8 warps, each 64x32).
// ---------------------------------------------------------------------------
constexpr int BM = 128, BN = 128, BK = 32;
constexpr int SSTRIDE = 36;
constexpr int TILE_WORDS = 128 * SSTRIDE;
#define SMEM_WORDS (4 * TILE_WORDS)               // 73728 B

__device__ __forceinline__
void gemm_body(const float4* __restrict__ A, const float4* __restrict__ B,
               float* __restrict__ C, uint32_t* smem)
{
    uint32_t* sA[2] = { smem,              smem + 2 * TILE_WORDS };
    uint32_t* sB[2] = { smem + TILE_WORDS, smem + 3 * TILE_WORDS };

    const int tid = threadIdx.x;
    const int wid = tid >> 5, lane = tid & 31;
    const int g    = lane >> 2;
    const int tid4 = lane & 3;
    const int warpM = wid >> 2;
    const int warpN = wid & 3;
    const int bm = blockIdx.y * BM, bn = blockIdx.x * BN;

    const int row0 = tid >> 3;
    const int c4   = tid & 7;

    const float4* Ag = A + (size_t)(bm + row0) * (DIM / 4) + c4;
    const float4* Bg = B + (size_t)(bn + row0) * (DIM / 4) + c4;

    float acc[4][4][4];
    #pragma unroll
    for (int i = 0; i < 4; i++)
        #pragma unroll
        for (int j = 0; j < 4; j++)
            #pragma unroll
            for (int q = 0; q < 4; q++)
                acc[i][j][q] = 0.f;

    float4 ra[4], rb[4];

    auto ldg_tile = [&](int kt) {
        const size_t ko = (size_t)kt * (BK / 4);
        #pragma unroll
        for (int i = 0; i < 4; i++) {
            ra[i] = Ag[ko + (size_t)(32 * i) * (DIM / 4)];
            rb[i] = Bg[ko + (size_t)(32 * i) * (DIM / 4)];
        }
    };
    auto sts_tile = [&](int b) {
        #pragma unroll
        for (int i = 0; i < 4; i++) {
            uint4 ta = { f2tf32(ra[i].x), f2tf32(ra[i].y), f2tf32(ra[i].z), f2tf32(ra[i].w) };
            uint4 tb = { f2tf32(rb[i].x), f2tf32(rb[i].y), f2tf32(rb[i].z), f2tf32(rb[i].w) };
            *reinterpret_cast<uint4*>(sA[b] + (row0 + 32 * i) * SSTRIDE + 4 * c4) = ta;
            *reinterpret_cast<uint4*>(sB[b] + (row0 + 32 * i) * SSTRIDE + 4 * c4) = tb;
        }
    };

    ldg_tile(0);
    sts_tile(0);
    __syncthreads();

    const int NKT = DIM / BK;
    for (int kt = 0; kt < NKT; kt++) {
        const int b = kt & 1;
        if (kt + 1 < NKT) ldg_tile(kt + 1);

        const uint32_t* Aw = sA[b] + (warpM * 64 + g) * SSTRIDE;
        const uint32_t* Bw = sB[b] + (warpN * 32 + g) * SSTRIDE;

        #pragma unroll
        for (int kk = 0; kk < 4; kk++) {
            const int kidx = kk * 8 + tid4;
            uint32_t af[4][4], bf[4][2];
            #pragma unroll
            for (int mt = 0; mt < 4; mt++) {
                af[mt][0] = Aw[(mt * 16)     * SSTRIDE + kidx];
                af[mt][1] = Aw[(mt * 16 + 8) * SSTRIDE + kidx];
                af[mt][2] = Aw[(mt * 16)     * SSTRIDE + kidx + 4];
                af[mt][3] = Aw[(mt * 16 + 8) * SSTRIDE + kidx + 4];
            }
            #pragma unroll
            for (int nt = 0; nt < 4; nt++) {
                bf[nt][0] = Bw[(nt * 8) * SSTRIDE + kidx];
                bf[nt][1] = Bw[(nt * 8) * SSTRIDE + kidx + 4];
            }
            #pragma unroll
            for (int mt = 0; mt < 4; mt++)
                #pragma unroll
                for (int nt = 0; nt < 4; nt++)
                    mma_tf32_16x8x8(acc[mt][nt],
                                    af[mt][0], af[mt][1], af[mt][2], af[mt][3],
                                    bf[nt][0], bf[nt][1]);
        }

        if (kt + 1 < NKT) {
            __syncthreads();
            sts_tile(b ^ 1);
            __syncthreads();
        }
    }

    #pragma unroll
    for (int mt = 0; mt < 4; mt++) {
        const int r0 = bm + warpM * 64 + mt * 16 + g;
        #pragma unroll
        for (int nt = 0; nt < 4; nt++) {
            const int col = bn + warpN * 32 + nt * 8 + 2 * tid4;
            *(float2*)(C + (size_t)r0 * DIM + col)       = make_float2(acc[mt][nt][0], acc[mt][nt][1]);
            *(float2*)(C + (size_t)(r0 + 8) * DIM + col) = make_float2(acc[mt][nt][2], acc[mt][nt][3]);
        }
    }
}

__global__ __launch_bounds__(256, 2)
void gemm_qkv(const float4* __restrict__ A,
              const float4* __restrict__ Bq, const float4* __restrict__ Bk,
              const float4* __restrict__ Bv,
              float* __restrict__ Cq, float* __restrict__ Ck, float* __restrict__ Cv)
{
    extern __shared__ uint32_t smem[];
    const int z = blockIdx.z;
    const float4* B = (z == 0) ? Bq : (z == 1) ? Bk : Bv;
    float* C       = (z == 0) ? Cq : (z == 1) ? Ck : Cv;
    gemm_body(A, B, C, smem);
}

__global__ __launch_bounds__(256, 2)
void gemm_tf32(const float4* __restrict__ A, const float4* __restrict__ B,
               float* __restrict__ C)
{
    extern __shared__ uint32_t smem[];
    gemm_body(A, B, C, smem);
}

// ---------------------------------------------------------------------------
// Windowed attention, fused RoPE. Register-tiled, float4 smem paths.
// Block = 1 window (1024 blocks), 256 threads = 4 head-groups of 64.
// Each group processes 4 heads sequentially. Per head:
//   stage: 64 threads stage roped q,k and v (16x64 each) into smem
//   scores: thread (rq, c) computes s[rq+4*rr][c], rr=0..3 (K row read once)
//   softmax: shuffle over 16 c-lanes
//   PV: thread computes out[rq+4*rr][4c..4c+3]
// ---------------------------------------------------------------------------
constexpr int QS = 68;          // row stride (floats) for sq/sk/sv
constexpr int PS = 20;          // row stride for sp
constexpr int GRP_WORDS = 3 * WIN * QS + WIN * PS;   // 3584
constexpr int ATTN_SMEM_WORDS = 1024 + 4 * GRP_WORDS; // 15360 -> 61440 B

__global__ __launch_bounds__(256)
void attn_kernel(const float* __restrict__ rope)
{
    extern __shared__ float sm[];
    float* cs = sm;               // [16][32]
    float* sn = sm + 512;         // [16][32]

    const int tid = threadIdx.x;
    const int hg  = tid >> 6;      // head group 0..3
    const int t   = tid & 63;      // id within group

    float* sq = sm + 1024 + hg * GRP_WORDS;
    float* sk = sq + WIN * QS;
    float* sv = sk + WIN * QS;
    float* sp = sv + WIN * QS;

    const int w = blockIdx.x;

    // cos/sin table, rope layout is exactly [16][32]
    for (int e = tid; e < 512; e += 256)
        sincosf(rope[e], &sn[e], &cs[e]);
    __syncthreads();

    // staging ids: row sr (0..15), quarter qt (0..3)
    const int sr = t >> 2, qt = t & 3;
    // compute ids
    const int lane = tid & 31;
    const int c  = lane & 15;
    const int rq = (lane >> 4) + 2 * ((t >> 5) & 1);   // 0..3

    for (int it = 0; it < 4; ++it) {
        const int h = hg * 4 + it;

        // ---- stage q (rope), k (rope), v ----
        {
            const size_t base = ((size_t)(w * WIN + sr)) * DIM + h * HD;
            const int d0 = qt * 8;

            float4 qa0 = *(const float4*)(g_q + base + d0);
            float4 qa1 = *(const float4*)(g_q + base + d0 + 4);
            float4 qb0 = *(const float4*)(g_q + base + d0 + 32);
            float4 qb1 = *(const float4*)(g_q + base + d0 + 36);
            float4 ka0 = *(const float4*)(g_k + base + d0);
            float4 ka1 = *(const float4*)(g_k + base + d0 + 4);
            float4 kb0 = *(const float4*)(g_k + base + d0 + 32);
            float4 kb1 = *(const float4*)(g_k + base + d0 + 36);

            float qa[8] = {qa0.x,qa0.y,qa0.z,qa0.w, qa1.x,qa1.y,qa1.z,qa1.w};
            float qb[8] = {qb0.x,qb0.y,qb0.z,qb0.w, qb1.x,qb1.y,qb1.z,qb1.w};
            float ka[8] = {ka0.x,ka0.y,ka0.z,ka0.w, ka1.x,ka1.y,ka1.z,ka1.w};
            float kb[8] = {kb0.x,kb0.y,kb0.z,kb0.w, kb1.x,kb1.y,kb1.z,kb1.w};

            float qlo[8], qhi[8], klo[8], khi[8];
            #pragma unroll
            for (int j = 0; j < 8; j++) {
                const float C_ = cs[sr * 32 + d0 + j];
                const float S_ = sn[sr * 32 + d0 + j];
                qlo[j] = qa[j] * C_ - qb[j] * S_;
                qhi[j] = qa[j] * S_ + qb[j] * C_;
                klo[j] = ka[j] * C_ - kb[j] * S_;
                khi[j] = ka[j] * S_ + kb[j] * C_;
            }
            float* qrow = sq + sr * QS;
            float* krow = sk + sr * QS;
            *(float4*)(qrow + d0)      = make_float4(qlo[0],qlo[1],qlo[2],qlo[3]);
            *(float4*)(qrow + d0 + 4)  = make_float4(qlo[4],qlo[5],qlo[6],qlo[7]);
            *(float4*)(qrow + d0 + 32) = make_float4(qhi[0],qhi[1],qhi[2],qhi[3]);
            *(float4*)(qrow + d0 + 36) = make_float4(qhi[4],qhi[5],qhi[6],qhi[7]);
            *(float4*)(krow + d0)      = make_float4(klo[0],klo[1],klo[2],klo[3]);
            *(float4*)(krow + d0 + 4)  = make_float4(klo[4],klo[5],klo[6],klo[7]);
            *(float4*)(krow + d0 + 32) = make_float4(khi[0],khi[1],khi[2],khi[3]);
            *(float4*)(krow + d0 + 36) = make_float4(khi[4],khi[5],khi[6],khi[7]);

            const int dv = qt * 16;
            float* vrow = sv + sr * QS;
            #pragma unroll
            for (int i = 0; i < 4; i++)
                *(float4*)(vrow + dv + 4 * i) = *(const float4*)(g_v + base + dv + 4 * i);
        }
        __syncthreads();

        // ---- scores: 4 rows per thread, K row read once ----
        float s0 = 0.f, s1 = 0.f, s2 = 0.f, s3 = 0.f;
        {
            const float* krow = sk + c * QS;
            const float* q0r = sq + rq * QS;
            const float* q1r = q0r + 4 * QS;
            const float* q2r = q0r + 8 * QS;
            const float* q3r = q0r + 12 * QS;
            #pragma unroll
            for (int j = 0; j < 16; j++) {
                float4 kf = *(const float4*)(krow + 4 * j);
                float4 q0 = *(const float4*)(q0r + 4 * j);
                float4 q1 = *(const float4*)(q1r + 4 * j);
                float4 q2 = *(const float4*)(q2r + 4 * j);
                float4 q3 = *(const float4*)(q3r + 4 * j);
                s0 = fmaf(q0.x,kf.x,fmaf(q0.y,kf.y,fmaf(q0.z,kf.z,fmaf(q0.w,kf.w,s0))));
                s1 = fmaf(q1.x,kf.x,fmaf(q1.y,kf.y,fmaf(q1.z,kf.z,fmaf(q1.w,kf.w,s1))));
                s2 = fmaf(q2.x,kf.x,fmaf(q2.y,kf.y,fmaf(q2.z,kf.z,fmaf(q2.w,kf.w,s2))));
                s3 = fmaf(q3.x,kf.x,fmaf(q3.y,kf.y,fmaf(q3.z,kf.z,fmaf(q3.w,kf.w,s3))));
            }
        }
        s0 *= 0.125f; s1 *= 0.125f; s2 *= 0.125f; s3 *= 0.125f;

        // ---- softmax over 16 c-lanes (offsets <= 8 stay in half-warp) ----
        float m0 = s0, m1 = s1, m2 = s2, m3 = s3;
        #pragma unroll
        for (int o = 8; o; o >>= 1) {
            m0 = fmaxf(m0, __shfl_xor_sync(0xffffffffu, m0, o));
            m1 = fmaxf(m1, __shfl_xor_sync(0xffffffffu, m1, o));
            m2 = fmaxf(m2, __shfl_xor_sync(0xffffffffu, m2, o));
            m3 = fmaxf(m3, __shfl_xor_sync(0xffffffffu, m3, o));
        }
        float e0 = expf(s0 - m0), e1 = expf(s1 - m1), e2 = expf(s2 - m2), e3 = expf(s3 - m3);
        float u0 = e0, u1 = e1, u2 = e2, u3 = e3;
        #pragma unroll
        for (int o = 8; o; o >>= 1) {
            u0 += __shfl_xor_sync(0xffffffffu, u0, o);
            u1 += __shfl_xor_sync(0xffffffffu, u1, o);
            u2 += __shfl_xor_sync(0xffffffffu, u2, o);
            u3 += __shfl_xor_sync(0xffffffffu, u3, o);
        }
        sp[(rq)      * PS + c] = e0 / u0;
        sp[(rq + 4)  * PS + c] = e1 / u1;
        sp[(rq + 8)  * PS + c] = e2 / u2;
        sp[(rq + 12) * PS + c] = e3 / u3;
        __syncwarp();

        // ---- PV: 4 rows x 4 d per thread ----
        float4 o0 = {0,0,0,0}, o1 = {0,0,0,0}, o2 = {0,0,0,0}, o3 = {0,0,0,0};
        #pragma unroll
        for (int kc = 0; kc < 4; kc++) {
            float4 p0 = *(const float4*)(sp + (rq)      * PS + 4 * kc);
            float4 p1 = *(const float4*)(sp + (rq + 4)  * PS + 4 * kc);
            float4 p2 = *(const float4*)(sp + (rq + 8)  * PS + 4 * kc);
            float4 p3 = *(const float4*)(sp + (rq + 12) * PS + 4 * kc);
            const float pa0[4] = {p0.x,p0.y,p0.z,p0.w};
            const float pa1[4] = {p1.x,p1.y,p1.z,p1.w};
            const float pa2[4] = {p2.x,p2.y,p2.z,p2.w};
            const float pa3[4] = {p3.x,p3.y,p3.z,p3.w};
            #pragma unroll
            for (int jj = 0; jj < 4; jj++) {
                float4 vf = *(const float4*)(sv + (4 * kc + jj) * QS + 4 * c);
                o0.x = fmaf(pa0[jj], vf.x, o0.x); o0.y = fmaf(pa0[jj], vf.y, o0.y);
                o0.z = fmaf(pa0[jj], vf.z, o0.z); o0.w = fmaf(pa0[jj], vf.w, o0.w);
                o1.x = fmaf(pa1[jj], vf.x, o1.x); o1.y = fmaf(pa1[jj], vf.y, o1.y);
                o1.z = fmaf(pa1[jj], vf.z, o1.z); o1.w = fmaf(pa1[jj], vf.w, o1.w);
                o2.x = fmaf(pa2[jj], vf.x, o2.x); o2.y = fmaf(pa2[jj], vf.y, o2.y);
                o2.z = fmaf(pa2[jj], vf.z, o2.z); o2.w = fmaf(pa2[jj], vf.w, o2.w);
                o3.x = fmaf(pa3[jj], vf.x, o3.x); o3.y = fmaf(pa3[jj], vf.y, o3.y);
                o3.z = fmaf(pa3[jj], vf.z, o3.z); o3.w = fmaf(pa3[jj], vf.w, o3.w);
            }
        }
        {
            const size_t ob = ((size_t)(w * WIN)) * DIM + h * HD + 4 * c;
            *(float4*)(g_attn + ob + (size_t)(rq)      * DIM) = o0;
            *(float4*)(g_attn + ob + (size_t)(rq + 4)  * DIM) = o1;
            *(float4*)(g_attn + ob + (size_t)(rq + 8)  * DIM) = o2;
            *(float4*)(g_attn + ob + (size_t)(rq + 12) * DIM) = o3;
        }
        __syncthreads();   // before next head's staging overwrites smem
    }
}

// ---------------------------------------------------------------------------
extern "C" void kernel_launch(void* const* d_in, const int* in_sizes, int n_in,
                              void* d_out, int out_size)
{
    const float* x    = (const float*)d_in[0];
    const float* rope = (const float*)d_in[1];
    const float* wq   = (const float*)d_in[2];
    const float* wk   = (const float*)d_in[3];
    const float* wv   = (const float*)d_in[4];
    const float* wo   = (const float*)d_in[5];
    float* out        = (float*)d_out;

    float *q, *k, *v, *attn;
    cudaGetSymbolAddress((void**)&q,    g_q);
    cudaGetSymbolAddress((void**)&k,    g_k);
    cudaGetSymbolAddress((void**)&v,    g_v);
    cudaGetSymbolAddress((void**)&attn, g_attn);

    cudaFuncSetAttribute(gemm_qkv,  cudaFuncAttributeMaxDynamicSharedMemorySize, SMEM_WORDS * 4);
    cudaFuncSetAttribute(gemm_tf32, cudaFuncAttributeMaxDynamicSharedMemorySize, SMEM_WORDS * 4);
    cudaFuncSetAttribute(attn_kernel, cudaFuncAttributeMaxDynamicSharedMemorySize,
                         ATTN_SMEM_WORDS * 4);

    size_t shmem = SMEM_WORDS * 4;
    dim3 grid_qkv(DIM / BN, NTOK / BM, 3);
    gemm_qkv<<<grid_qkv, 256, shmem>>>((const float4*)x,
                                       (const float4*)wq, (const float4*)wk, (const float4*)wv,
                                       q, k, v);

    attn_kernel<<<NWIN, 256, ATTN_SMEM_WORDS * 4>>>(rope);

    dim3 grid(DIM / BN, NTOK / BM);
    gemm_tf32<<<grid, 256, shmem>>>((const float4*)attn, (const float4*)wo, out);
}

// round 5
// speedup vs baseline: 2.8777x; 1.0459x over previous
#include <cuda_runtime.h>
#include <cstdint>
#include <math.h>

#define DIM    1024
#define HEADS  16
#define HD     64
#define WIN    16
#define NTOK   16384   // B*S
#define NWIN   1024

// Scratch (allocation-free rule: __device__ globals)
__device__ __align__(16) float g_q[NTOK * DIM];
__device__ __align__(16) float g_k[NTOK * DIM];
__device__ __align__(16) float g_v[NTOK * DIM];
__device__ __align__(16) float g_attn[NTOK * DIM];
__device__ __align__(16) float g_xr[NTOK * DIM];    // tf32-rounded x
__device__ __align__(16) float g_wq[DIM * DIM];
__device__ __align__(16) float g_wk[DIM * DIM];
__device__ __align__(16) float g_wv[DIM * DIM];
__device__ __align__(16) float g_wo[DIM * DIM];

// ---------------------------------------------------------------------------
// helpers
// ---------------------------------------------------------------------------
__device__ __forceinline__ uint32_t smem_u32(const void* p) {
    uint32_t a;
    asm("{ .reg .u64 t; cvta.to.shared.u64 t, %1; cvt.u32.u64 %0, t; }"
        : "=r"(a) : "l"(p));
    return a;
}
__device__ __forceinline__ uint32_t f2tf32(float f) {
    uint32_t r;
    asm("cvt.rna.tf32.f32 %0, %1;" : "=r"(r) : "f"(f));
    return r;
}
__device__ __forceinline__ float rtf(float f) { return __uint_as_float(f2tf32(f)); }

__device__ __forceinline__ void cp_async16(uint32_t dst, const void* src) {
    asm volatile("cp.async.cg.shared.global [%0], [%1], 16;"
                 :: "r"(dst), "l"(src) : "memory");
}
__device__ __forceinline__ void cp_commit() {
    asm volatile("cp.async.commit_group;" ::: "memory");
}
template <int N>
__device__ __forceinline__ void cp_wait() {
    asm volatile("cp.async.wait_group %0;" :: "n"(N) : "memory");
}
__device__ __forceinline__ void ldsm_x4(uint32_t r[4], uint32_t addr) {
    asm volatile("ldmatrix.sync.aligned.m8n8.x4.shared.b16 {%0,%1,%2,%3}, [%4];"
                 : "=r"(r[0]), "=r"(r[1]), "=r"(r[2]), "=r"(r[3]) : "r"(addr));
}
__device__ __forceinline__ void mma_tf32_16x8x8(float c[4],
                                                uint32_t a0, uint32_t a1,
                                                uint32_t a2, uint32_t a3,
                                                uint32_t b0, uint32_t b1) {
    asm volatile(
        "mma.sync.aligned.m16n8k8.row.col.f32.tf32.tf32.f32 "
        "{%0,%1,%2,%3}, {%4,%5,%6,%7}, {%8,%9}, {%0,%1,%2,%3};"
        : "+f"(c[0]), "+f"(c[1]), "+f"(c[2]), "+f"(c[3])
        : "r"(a0), "r"(a1), "r"(a2), "r"(a3), "r"(b0), "r"(b1));
}

// ---------------------------------------------------------------------------
// tf32 mma.sync GEMM: C[M,N] = A[M,K]*B[N,K]^T ; inputs pre-rounded to tf32.
// CTA 256x128, BK=32, 256 threads = 8 warps of 64x64. cp.async staging,
// ldmatrix fragments. Smem row stride 36 words (144 B), double buffered.
// ---------------------------------------------------------------------------
constexpr int BM = 256, BN = 128, BK = 32;
constexpr int SSW      = 36;                 // words per smem row
constexpr int A_BYTES  = BM * SSW * 4;       // 36864
constexpr int B_BYTES  = BN * SSW * 4;       // 18432
constexpr int BUF_BYTES = A_BYTES + B_BYTES; // 55296
constexpr int GSMEM    = 2 * BUF_BYTES;      // 110592

__device__ __forceinline__
void gemm_body(const float4* __restrict__ A, const float4* __restrict__ B,
               float* __restrict__ C)
{
    extern __shared__ uint32_t sm[];
    const uint32_t sbu = smem_u32(sm);

    const int tid  = threadIdx.x;
    const int lane = tid & 31, wid = tid >> 5;
    const int g = lane >> 2, tid4 = lane & 3;
    const int warpM = wid >> 1;               // 0..3
    const int warpN = wid & 1;                // 0..1
    const int bm = blockIdx.y * BM, bn = blockIdx.x * BN;

    // staging: A 2048 float4 (8/thread), B 1024 float4 (4/thread)
    const int srow = tid >> 3, sc4 = tid & 7;
    const float4* Ag = A + (size_t)(bm + srow) * (DIM / 4) + sc4;
    const float4* Bg = B + (size_t)(bn + srow) * (DIM / 4) + sc4;
    const uint32_t sdA = sbu + srow * 144 + sc4 * 16;
    const uint32_t sdB = sbu + A_BYTES + srow * 144 + sc4 * 16;

    auto stage = [&](int b, int kt) {
        const uint32_t bo = b * BUF_BYTES;
        const size_t ko = (size_t)kt * 8;
        #pragma unroll
        for (int i = 0; i < 8; i++)
            cp_async16(sdA + bo + i * 4608, Ag + ko + (size_t)(32 * i) * (DIM / 4));
        #pragma unroll
        for (int i = 0; i < 4; i++)
            cp_async16(sdB + bo + i * 4608, Bg + ko + (size_t)(32 * i) * (DIM / 4));
        cp_commit();
    };

    // ldmatrix lane offsets (row = lane&15, +16B for upper half-lanes)
    const uint32_t aoff = (warpM * 64 + (lane & 15)) * 144 + ((lane >> 4) << 4);
    const uint32_t boff = A_BYTES + (warpN * 64 + (lane & 15)) * 144 + ((lane >> 4) << 4);

    float acc[4][8][4];
    #pragma unroll
    for (int i = 0; i < 4; i++)
        #pragma unroll
        for (int j = 0; j < 8; j++)
            #pragma unroll
            for (int q = 0; q < 4; q++)
                acc[i][j][q] = 0.f;

    stage(0, 0);

    const int NKT = DIM / BK;   // 32
    for (int kt = 0; kt < NKT; kt++) {
        const int b = kt & 1;
        if (kt + 1 < NKT) { stage(b ^ 1, kt + 1); cp_wait<1>(); }
        else              { cp_wait<0>(); }
        __syncthreads();

        const uint32_t ab = sbu + b * BUF_BYTES + aoff;
        const uint32_t bb = sbu + b * BUF_BYTES + boff;

        #pragma unroll
        for (int kk = 0; kk < 4; kk++) {
            uint32_t af[4][4], bf[4][4];
            #pragma unroll
            for (int mt = 0; mt < 4; mt++)
                ldsm_x4(af[mt], ab + mt * 2304 + kk * 32);
            #pragma unroll
            for (int p = 0; p < 4; p++)
                ldsm_x4(bf[p], bb + p * 2304 + kk * 32);
            #pragma unroll
            for (int mt = 0; mt < 4; mt++)
                #pragma unroll
                for (int p = 0; p < 4; p++) {
                    mma_tf32_16x8x8(acc[mt][2 * p],
                                    af[mt][0], af[mt][1], af[mt][2], af[mt][3],
                                    bf[p][0], bf[p][2]);
                    mma_tf32_16x8x8(acc[mt][2 * p + 1],
                                    af[mt][0], af[mt][1], af[mt][2], af[mt][3],
                                    bf[p][1], bf[p][3]);
                }
        }
        __syncthreads();   // all reads of buf b done before it is re-staged
    }

    // epilogue
    #pragma unroll
    for (int mt = 0; mt < 4; mt++) {
        const int r0 = bm + warpM * 64 + mt * 16 + g;
        #pragma unroll
        for (int nt = 0; nt < 8; nt++) {
            const int col = bn + warpN * 64 + nt * 8 + 2 * tid4;
            *(float2*)(C + (size_t)r0 * DIM + col) =
                make_float2(acc[mt][nt][0], acc[mt][nt][1]);
            *(float2*)(C + (size_t)(r0 + 8) * DIM + col) =
                make_float2(acc[mt][nt][2], acc[mt][nt][3]);
        }
    }
}

__global__ __launch_bounds__(256, 1)
void gemm_qkv(const float4* __restrict__ A,
              const float4* __restrict__ Bq, const float4* __restrict__ Bk,
              const float4* __restrict__ Bv,
              float* __restrict__ Cq, float* __restrict__ Ck, float* __restrict__ Cv)
{
    const int z = blockIdx.z;
    const float4* B = (z == 0) ? Bq : (z == 1) ? Bk : Bv;
    float* C       = (z == 0) ? Cq : (z == 1) ? Ck : Cv;
    gemm_body(A, B, C);
}

__global__ __launch_bounds__(256, 1)
void gemm_tc(const float4* __restrict__ A, const float4* __restrict__ B,
             float* __restrict__ C)
{
    gemm_body(A, B, C);
}

// ---------------------------------------------------------------------------
// tf32 rounding prepass (elementwise copy with cvt.rna.tf32)
// ---------------------------------------------------------------------------
__global__ void round_tf32(const float4* __restrict__ src, float4* __restrict__ dst,
                           int n4)
{
    int i = blockIdx.x * blockDim.x + threadIdx.x;
    const int stride = gridDim.x * blockDim.x;
    for (; i < n4; i += stride) {
        float4 v = src[i];
        dst[i] = make_float4(rtf(v.x), rtf(v.y), rtf(v.z), rtf(v.w));
    }
}

// ---------------------------------------------------------------------------
// Windowed attention, fused RoPE (R4 layout). Output rounded to tf32 so the
// WO GEMM can consume it via cp.async without a conversion pass.
// ---------------------------------------------------------------------------
constexpr int QS = 68;
constexpr int PS = 20;
constexpr int GRP_WORDS = 3 * WIN * QS + WIN * PS;     // 3584
constexpr int ATTN_SMEM_WORDS = 1024 + 4 * GRP_WORDS;  // 15360 -> 61440 B

__global__ __launch_bounds__(256)
void attn_kernel(const float* __restrict__ rope)
{
    extern __shared__ float smf[];
    float* cs = smf;
    float* sn = smf + 512;

    const int tid = threadIdx.x;
    const int hg  = tid >> 6;
    const int t   = tid & 63;

    float* sq = smf + 1024 + hg * GRP_WORDS;
    float* sk = sq + WIN * QS;
    float* sv = sk + WIN * QS;
    float* sp = sv + WIN * QS;

    const int w = blockIdx.x;

    for (int e = tid; e < 512; e += 256)
        sincosf(rope[e], &sn[e], &cs[e]);
    __syncthreads();

    const int sr = t >> 2, qt = t & 3;
    const int lane = tid & 31;
    const int c  = lane & 15;
    const int rq = (lane >> 4) + 2 * ((t >> 5) & 1);

    for (int it = 0; it < 4; ++it) {
        const int h = hg * 4 + it;

        {
            const size_t base = ((size_t)(w * WIN + sr)) * DIM + h * HD;
            const int d0 = qt * 8;

            float4 qa0 = *(const float4*)(g_q + base + d0);
            float4 qa1 = *(const float4*)(g_q + base + d0 + 4);
            float4 qb0 = *(const float4*)(g_q + base + d0 + 32);
            float4 qb1 = *(const float4*)(g_q + base + d0 + 36);
            float4 ka0 = *(const float4*)(g_k + base + d0);
            float4 ka1 = *(const float4*)(g_k + base + d0 + 4);
            float4 kb0 = *(const float4*)(g_k + base + d0 + 32);
            float4 kb1 = *(const float4*)(g_k + base + d0 + 36);

            float qa[8] = {qa0.x,qa0.y,qa0.z,qa0.w, qa1.x,qa1.y,qa1.z,qa1.w};
            float qb[8] = {qb0.x,qb0.y,qb0.z,qb0.w, qb1.x,qb1.y,qb1.z,qb1.w};
            float ka[8] = {ka0.x,ka0.y,ka0.z,ka0.w, ka1.x,ka1.y,ka1.z,ka1.w};
            float kb[8] = {kb0.x,kb0.y,kb0.z,kb0.w, kb1.x,kb1.y,kb1.z,kb1.w};

            float qlo[8], qhi[8], klo[8], khi[8];
            #pragma unroll
            for (int j = 0; j < 8; j++) {
                const float C_ = cs[sr * 32 + d0 + j];
                const float S_ = sn[sr * 32 + d0 + j];
                qlo[j] = qa[j] * C_ - qb[j] * S_;
                qhi[j] = qa[j] * S_ + qb[j] * C_;
                klo[j] = ka[j] * C_ - kb[j] * S_;
                khi[j] = ka[j] * S_ + kb[j] * C_;
            }
            float* qrow = sq + sr * QS;
            float* krow = sk + sr * QS;
            *(float4*)(qrow + d0)      = make_float4(qlo[0],qlo[1],qlo[2],qlo[3]);
            *(float4*)(qrow + d0 + 4)  = make_float4(qlo[4],qlo[5],qlo[6],qlo[7]);
            *(float4*)(qrow + d0 + 32) = make_float4(qhi[0],qhi[1],qhi[2],qhi[3]);
            *(float4*)(qrow + d0 + 36) = make_float4(qhi[4],qhi[5],qhi[6],qhi[7]);
            *(float4*)(krow + d0)      = make_float4(klo[0],klo[1],klo[2],klo[3]);
            *(float4*)(krow + d0 + 4)  = make_float4(klo[4],klo[5],klo[6],klo[7]);
            *(float4*)(krow + d0 + 32) = make_float4(khi[0],khi[1],khi[2],khi[3]);
            *(float4*)(krow + d0 + 36) = make_float4(khi[4],khi[5],khi[6],khi[7]);

            const int dv = qt * 16;
            float* vrow = sv + sr * QS;
            #pragma unroll
            for (int i = 0; i < 4; i++)
                *(float4*)(vrow + dv + 4 * i) = *(const float4*)(g_v + base + dv + 4 * i);
        }
        __syncthreads();

        float s0 = 0.f, s1 = 0.f, s2 = 0.f, s3 = 0.f;
        {
            const float* krow = sk + c * QS;
            const float* q0r = sq + rq * QS;
            const float* q1r = q0r + 4 * QS;
            const float* q2r = q0r + 8 * QS;
            const float* q3r = q0r + 12 * QS;
            #pragma unroll
            for (int j = 0; j < 16; j++) {
                float4 kf = *(const float4*)(krow + 4 * j);
                float4 q0 = *(const float4*)(q0r + 4 * j);
                float4 q1 = *(const float4*)(q1r + 4 * j);
                float4 q2 = *(const float4*)(q2r + 4 * j);
                float4 q3 = *(const float4*)(q3r + 4 * j);
                s0 = fmaf(q0.x,kf.x,fmaf(q0.y,kf.y,fmaf(q0.z,kf.z,fmaf(q0.w,kf.w,s0))));
                s1 = fmaf(q1.x,kf.x,fmaf(q1.y,kf.y,fmaf(q1.z,kf.z,fmaf(q1.w,kf.w,s1))));
                s2 = fmaf(q2.x,kf.x,fmaf(q2.y,kf.y,fmaf(q2.z,kf.z,fmaf(q2.w,kf.w,s2))));
                s3 = fmaf(q3.x,kf.x,fmaf(q3.y,kf.y,fmaf(q3.z,kf.z,fmaf(q3.w,kf.w,s3))));
            }
        }
        s0 *= 0.125f; s1 *= 0.125f; s2 *= 0.125f; s3 *= 0.125f;

        float m0 = s0, m1 = s1, m2 = s2, m3 = s3;
        #pragma unroll
        for (int o = 8; o; o >>= 1) {
            m0 = fmaxf(m0, __shfl_xor_sync(0xffffffffu, m0, o));
            m1 = fmaxf(m1, __shfl_xor_sync(0xffffffffu, m1, o));
            m2 = fmaxf(m2, __shfl_xor_sync(0xffffffffu, m2, o));
            m3 = fmaxf(m3, __shfl_xor_sync(0xffffffffu, m3, o));
        }
        float e0 = expf(s0 - m0), e1 = expf(s1 - m1), e2 = expf(s2 - m2), e3 = expf(s3 - m3);
        float u0 = e0, u1 = e1, u2 = e2, u3 = e3;
        #pragma unroll
        for (int o = 8; o; o >>= 1) {
            u0 += __shfl_xor_sync(0xffffffffu, u0, o);
            u1 += __shfl_xor_sync(0xffffffffu, u1, o);
            u2 += __shfl_xor_sync(0xffffffffu, u2, o);
            u3 += __shfl_xor_sync(0xffffffffu, u3, o);
        }
        sp[(rq)      * PS + c] = e0 / u0;
        sp[(rq + 4)  * PS + c] = e1 / u1;
        sp[(rq + 8)  * PS + c] = e2 / u2;
        sp[(rq + 12) * PS + c] = e3 / u3;
        __syncwarp();

        float4 o0 = {0,0,0,0}, o1 = {0,0,0,0}, o2 = {0,0,0,0}, o3 = {0,0,0,0};
        #pragma unroll
        for (int kc = 0; kc < 4; kc++) {
            float4 p0 = *(const float4*)(sp + (rq)      * PS + 4 * kc);
            float4 p1 = *(const float4*)(sp + (rq + 4)  * PS + 4 * kc);
            float4 p2 = *(const float4*)(sp + (rq + 8)  * PS + 4 * kc);
            float4 p3 = *(const float4*)(sp + (rq + 12) * PS + 4 * kc);
            const float pa0[4] = {p0.x,p0.y,p0.z,p0.w};
            const float pa1[4] = {p1.x,p1.y,p1.z,p1.w};
            const float pa2[4] = {p2.x,p2.y,p2.z,p2.w};
            const float pa3[4] = {p3.x,p3.y,p3.z,p3.w};
            #pragma unroll
            for (int jj = 0; jj < 4; jj++) {
                float4 vf = *(const float4*)(sv + (4 * kc + jj) * QS + 4 * c);
                o0.x = fmaf(pa0[jj], vf.x, o0.x); o0.y = fmaf(pa0[jj], vf.y, o0.y);
                o0.z = fmaf(pa0[jj], vf.z, o0.z); o0.w = fmaf(pa0[jj], vf.w, o0.w);
                o1.x = fmaf(pa1[jj], vf.x, o1.x); o1.y = fmaf(pa1[jj], vf.y, o1.y);
                o1.z = fmaf(pa1[jj], vf.z, o1.z); o1.w = fmaf(pa1[jj], vf.w, o1.w);
                o2.x = fmaf(pa2[jj], vf.x, o2.x); o2.y = fmaf(pa2[jj], vf.y, o2.y);
                o2.z = fmaf(pa2[jj], vf.z, o2.z); o2.w = fmaf(pa2[jj], vf.w, o2.w);
                o3.x = fmaf(pa3[jj], vf.x, o3.x); o3.y = fmaf(pa3[jj], vf.y, o3.y);
                o3.z = fmaf(pa3[jj], vf.z, o3.z); o3.w = fmaf(pa3[jj], vf.w, o3.w);
            }
        }
        {
            const size_t ob = ((size_t)(w * WIN)) * DIM + h * HD + 4 * c;
            *(float4*)(g_attn + ob + (size_t)(rq)      * DIM) =
                make_float4(rtf(o0.x), rtf(o0.y), rtf(o0.z), rtf(o0.w));
            *(float4*)(g_attn + ob + (size_t)(rq + 4)  * DIM) =
                make_float4(rtf(o1.x), rtf(o1.y), rtf(o1.z), rtf(o1.w));
            *(float4*)(g_attn + ob + (size_t)(rq + 8)  * DIM) =
                make_float4(rtf(o2.x), rtf(o2.y), rtf(o2.z), rtf(o2.w));
            *(float4*)(g_attn + ob + (size_t)(rq + 12) * DIM) =
                make_float4(rtf(o3.x), rtf(o3.y), rtf(o3.z), rtf(o3.w));
        }
        __syncthreads();
    }
}

// ---------------------------------------------------------------------------
extern "C" void kernel_launch(void* const* d_in, const int* in_sizes, int n_in,
                              void* d_out, int out_size)
{
    const float* x    = (const float*)d_in[0];
    const float* rope = (const float*)d_in[1];
    const float* wq   = (const float*)d_in[2];
    const float* wk   = (const float*)d_in[3];
    const float* wv   = (const float*)d_in[4];
    const float* wo   = (const float*)d_in[5];
    float* out        = (float*)d_out;

    float *q, *k, *v, *attn, *xr, *rwq, *rwk, *rwv, *rwo;
    cudaGetSymbolAddress((void**)&q,    g_q);
    cudaGetSymbolAddress((void**)&k,    g_k);
    cudaGetSymbolAddress((void**)&v,    g_v);
    cudaGetSymbolAddress((void**)&attn, g_attn);
    cudaGetSymbolAddress((void**)&xr,   g_xr);
    cudaGetSymbolAddress((void**)&rwq,  g_wq);
    cudaGetSymbolAddress((void**)&rwk,  g_wk);
    cudaGetSymbolAddress((void**)&rwv,  g_wv);
    cudaGetSymbolAddress((void**)&rwo,  g_wo);

    cudaFuncSetAttribute(gemm_qkv, cudaFuncAttributeMaxDynamicSharedMemorySize, GSMEM);
    cudaFuncSetAttribute(gemm_tc,  cudaFuncAttributeMaxDynamicSharedMemorySize, GSMEM);
    cudaFuncSetAttribute(attn_kernel, cudaFuncAttributeMaxDynamicSharedMemorySize,
                         ATTN_SMEM_WORDS * 4);

    // tf32 rounding prepass
    round_tf32<<<2048, 256>>>((const float4*)x,  (float4*)xr,  NTOK * DIM / 4);
    round_tf32<<<512, 256>>>((const float4*)wq, (float4*)rwq, DIM * DIM / 4);
    round_tf32<<<512, 256>>>((const float4*)wk, (float4*)rwk, DIM * DIM / 4);
    round_tf32<<<512, 256>>>((const float4*)wv, (float4*)rwv, DIM * DIM / 4);
    round_tf32<<<512, 256>>>((const float4*)wo, (float4*)rwo, DIM * DIM / 4);

    dim3 grid_qkv(DIM / BN, NTOK / BM, 3);   // (8, 64, 3)
    gemm_qkv<<<grid_qkv, 256, GSMEM>>>((const float4*)xr,
                                       (const float4*)rwq, (const float4*)rwk,
                                       (const float4*)rwv, q, k, v);

    attn_kernel<<<NWIN, 256, ATTN_SMEM_WORDS * 4>>>(rope);

    dim3 grid(DIM / BN, NTOK / BM);          // (8, 64)
    gemm_tc<<<grid, 256, GSMEM>>>((const float4*)attn, (const float4*)rwo, out);
}

// round 6
// speedup vs baseline: 5.2108x; 1.8108x over previous
#include <cuda_runtime.h>
#include <cuda_fp16.h>
#include <cstdint>
#include <math.h>

#define DIM    1024
#define HEADS  16
#define HD     64
#define WIN    16
#define NTOK   16384   // B*S
#define NWIN   1024

// Scratch (allocation-free rule: __device__ globals)
__device__ __align__(16) float  g_q[NTOK * DIM];
__device__ __align__(16) float  g_k[NTOK * DIM];
__device__ __align__(16) float  g_v[NTOK * DIM];
__device__ __align__(16) __half g_attnh[NTOK * DIM];
__device__ __align__(16) __half g_xh[NTOK * DIM];
__device__ __align__(16) __half g_wqh[DIM * DIM];
__device__ __align__(16) __half g_wkh[DIM * DIM];
__device__ __align__(16) __half g_wvh[DIM * DIM];
__device__ __align__(16) __half g_woh[DIM * DIM];

// ---------------------------------------------------------------------------
// helpers
// ---------------------------------------------------------------------------
__device__ __forceinline__ uint32_t smem_u32(const void* p) {
    uint32_t a;
    asm("{ .reg .u64 t; cvta.to.shared.u64 t, %1; cvt.u32.u64 %0, t; }"
        : "=r"(a) : "l"(p));
    return a;
}
__device__ __forceinline__ void cp_async16(uint32_t dst, const void* src) {
    asm volatile("cp.async.cg.shared.global [%0], [%1], 16;"
                 :: "r"(dst), "l"(src) : "memory");
}
__device__ __forceinline__ void cp_commit() {
    asm volatile("cp.async.commit_group;" ::: "memory");
}
template <int N>
__device__ __forceinline__ void cp_wait() {
    asm volatile("cp.async.wait_group %0;" :: "n"(N) : "memory");
}
__device__ __forceinline__ void ldsm_x4(uint32_t r[4], uint32_t addr) {
    asm volatile("ldmatrix.sync.aligned.m8n8.x4.shared.b16 {%0,%1,%2,%3}, [%4];"
                 : "=r"(r[0]), "=r"(r[1]), "=r"(r[2]), "=r"(r[3]) : "r"(addr));
}
__device__ __forceinline__ void mma_f16_16x8x16(float c[4],
                                                uint32_t a0, uint32_t a1,
                                                uint32_t a2, uint32_t a3,
                                                uint32_t b0, uint32_t b1) {
    asm volatile(
        "mma.sync.aligned.m16n8k16.row.col.f32.f16.f16.f32 "
        "{%0,%1,%2,%3}, {%4,%5,%6,%7}, {%8,%9}, {%0,%1,%2,%3};"
        : "+f"(c[0]), "+f"(c[1]), "+f"(c[2]), "+f"(c[3])
        : "r"(a0), "r"(a1), "r"(a2), "r"(a3), "r"(b0), "r"(b1));
}

// ---------------------------------------------------------------------------
// fp16 mma.sync GEMM: C[M,N] = A[M,K]*B[N,K]^T, fp32 accum.
// CTA 256x128, BK=64, 256 threads = 8 warps of 64x64.
// 3-stage cp.async pipeline, ldmatrix fragments, 144B smem row stride.
// ---------------------------------------------------------------------------
constexpr int BM = 256, BN = 128, BK = 64;
constexpr int ROWB   = 144;                 // bytes per smem row (128 data + 16 pad)
constexpr int A_SZ   = BM * ROWB;           // 36864
constexpr int B_SZ   = BN * ROWB;           // 18432
constexpr int STG_SZ = A_SZ + B_SZ;         // 55296
constexpr int NSTG   = 3;
constexpr int GSMEM  = NSTG * STG_SZ;       // 165888

__device__ __forceinline__
void gemm_body(const __half* __restrict__ A, const __half* __restrict__ B,
               float* __restrict__ C)
{
    extern __shared__ uint32_t sm[];
    const uint32_t sbu = smem_u32(sm);

    const int tid  = threadIdx.x;
    const int lane = tid & 31, wid = tid >> 5;
    const int g = lane >> 2, tid4 = lane & 3;
    const int warpM = wid >> 1;                // 0..3
    const int warpN = wid & 1;                 // 0..1
    const int bm = blockIdx.y * BM, bn = blockIdx.x * BN;

    // staging: A 2048 chunks of 16B (8/thread), B 1024 (4/thread)
    const int arow = tid >> 3, acc8 = tid & 7;     // pass covers 32 A rows / 32 B rows
    const __half* Ag = A + (size_t)(bm + arow) * DIM + acc8 * 8;
    const __half* Bg = B + (size_t)(bn + arow) * DIM + acc8 * 8;
    const uint32_t sdA = sbu + arow * ROWB + acc8 * 16;
    const uint32_t sdB = sbu + A_SZ + arow * ROWB + acc8 * 16;

    auto stage = [&](int s, int kt) {
        const uint32_t so = s * STG_SZ;
        const size_t ko = (size_t)kt * BK;
        #pragma unroll
        for (int i = 0; i < 8; i++)
            cp_async16(sdA + so + i * 32 * ROWB, Ag + ko + (size_t)(32 * i) * DIM);
        #pragma unroll
        for (int i = 0; i < 4; i++)
            cp_async16(sdB + so + i * 32 * ROWB, Bg + ko + (size_t)(32 * i) * DIM);
    };

    // ldmatrix lane offsets
    const uint32_t aoff = (warpM * 64 + (lane & 15)) * ROWB + ((lane >> 4) << 4);
    const uint32_t boff = A_SZ + (warpN * 64 + (lane & 15)) * ROWB + ((lane >> 4) << 4);

    float acc[4][8][4];
    #pragma unroll
    for (int i = 0; i < 4; i++)
        #pragma unroll
        for (int j = 0; j < 8; j++)
            #pragma unroll
            for (int q = 0; q < 4; q++)
                acc[i][j][q] = 0.f;

    stage(0, 0); cp_commit();
    stage(1, 1); cp_commit();

    const int NKT = DIM / BK;   // 16
    int s = 0;
    for (int kt = 0; kt < NKT; kt++) {
        cp_wait<1>();
        __syncthreads();

        // prefetch tile kt+2 into the stage consumed at kt-1
        if (kt + 2 < NKT) stage((s + 2) % NSTG, kt + 2);
        cp_commit();   // possibly-empty group keeps wait accounting uniform

        const uint32_t ab = sbu + s * STG_SZ + aoff;
        const uint32_t bb = sbu + s * STG_SZ + boff;

        #pragma unroll
        for (int ks = 0; ks < 4; ks++) {        // 4 k16 steps per BK=64
            uint32_t af[4][4], bf[2][4];
            #pragma unroll
            for (int mt = 0; mt < 4; mt++)
                ldsm_x4(af[mt], ab + mt * 16 * ROWB + ks * 32);
            #pragma unroll
            for (int p = 0; p < 2; p++)
                ldsm_x4(bf[p], bb + p * 16 * ROWB + ks * 32);
            #pragma unroll
            for (int mt = 0; mt < 4; mt++)
                #pragma unroll
                for (int p = 0; p < 2; p++) {
                    mma_f16_16x8x16(acc[mt][4 * p],
                                    af[mt][0], af[mt][1], af[mt][2], af[mt][3],
                                    bf[p][0], bf[p][2]);
                    mma_f16_16x8x16(acc[mt][4 * p + 1],
                                    af[mt][0], af[mt][1], af[mt][2], af[mt][3],
                                    bf[p][1], bf[p][3]);
                }
            // second pair of n8 tiles: reload B for upper 32 n-rows
            uint32_t bg[2][4];
            #pragma unroll
            for (int p = 0; p < 2; p++)
                ldsm_x4(bg[p], bb + (2 + p) * 16 * ROWB + ks * 32);
            #pragma unroll
            for (int mt = 0; mt < 4; mt++)
                #pragma unroll
                for (int p = 0; p < 2; p++) {
                    mma_f16_16x8x16(acc[mt][4 * p + 2],
                                    af[mt][0], af[mt][1], af[mt][2], af[mt][3],
                                    bg[p][0], bg[p][2]);
                    mma_f16_16x8x16(acc[mt][4 * p + 3],
                                    af[mt][0], af[mt][1], af[mt][2], af[mt][3],
                                    bg[p][1], bg[p][3]);
                }
        }
        s = (s + 1) % NSTG;
    }

    // epilogue: warp covers 64(M) x 64(N); nt order: p*4 groups map n = p*32 + q*8
    #pragma unroll
    for (int mt = 0; mt < 4; mt++) {
        const int r0 = bm + warpM * 64 + mt * 16 + g;
        #pragma unroll
        for (int p = 0; p < 2; p++)
            #pragma unroll
            for (int q = 0; q < 4; q++) {
                // acc[mt][4p+q] covers n-tile (p*32 + q*8): tiles 0,1 low pair, 2,3 high pair
                const int ncol = bn + warpN * 64 + p * 16 + (q & 1) * 8 + (q >> 1) * 32;
                float* c0 = C + (size_t)r0 * DIM + ncol + 2 * tid4;
                *(float2*)c0 = make_float2(acc[mt][4 * p + q][0], acc[mt][4 * p + q][1]);
                *(float2*)(c0 + 8 * DIM) = make_float2(acc[mt][4 * p + q][2], acc[mt][4 * p + q][3]);
            }
    }
}

__global__ __launch_bounds__(256, 1)
void gemm_qkv(const __half* __restrict__ A,
              float* __restrict__ Cq, float* __restrict__ Ck, float* __restrict__ Cv)
{
    const int z = blockIdx.z;
    const __half* B = (z == 0) ? g_wqh : (z == 1) ? g_wkh : g_wvh;
    float* C        = (z == 0) ? Cq : (z == 1) ? Ck : Cv;
    gemm_body(A, B, C);
}

__global__ __launch_bounds__(256, 1)
void gemm_wo(float* __restrict__ C)
{
    gemm_body(g_attnh, g_woh, C);
}

// ---------------------------------------------------------------------------
// fp32 -> fp16 conversion prepass
// ---------------------------------------------------------------------------
__global__ void f2h(const float4* __restrict__ src, uint2* __restrict__ dst, int n4)
{
    int i = blockIdx.x * blockDim.x + threadIdx.x;
    const int stride = gridDim.x * blockDim.x;
    for (; i < n4; i += stride) {
        float4 v = src[i];
        __half2 lo = __floats2half2_rn(v.x, v.y);
        __half2 hi = __floats2half2_rn(v.z, v.w);
        dst[i] = make_uint2(*(uint32_t*)&lo, *(uint32_t*)&hi);
    }
}

__global__ void f2h_w(const float4* __restrict__ w0, const float4* __restrict__ w1,
                      const float4* __restrict__ w2, const float4* __restrict__ w3)
{
    const int z = blockIdx.z;
    const float4* src = (z == 0) ? w0 : (z == 1) ? w1 : (z == 2) ? w2 : w3;
    uint2* dst = (uint2*)((z == 0) ? g_wqh : (z == 1) ? g_wkh : (z == 2) ? g_wvh : g_woh);
    const int n4 = DIM * DIM / 4;
    int i = blockIdx.x * blockDim.x + threadIdx.x;
    const int stride = gridDim.x * blockDim.x;
    for (; i < n4; i += stride) {
        float4 v = src[i];
        __half2 lo = __floats2half2_rn(v.x, v.y);
        __half2 hi = __floats2half2_rn(v.z, v.w);
        dst[i] = make_uint2(*(uint32_t*)&lo, *(uint32_t*)&hi);
    }
}

// ---------------------------------------------------------------------------
// Windowed attention, fused RoPE (R4 layout); output written as fp16.
// ---------------------------------------------------------------------------
constexpr int QS = 68;
constexpr int PS = 20;
constexpr int GRP_WORDS = 3 * WIN * QS + WIN * PS;
constexpr int ATTN_SMEM_WORDS = 1024 + 4 * GRP_WORDS;

__global__ __launch_bounds__(256)
void attn_kernel(const float* __restrict__ rope)
{
    extern __shared__ float smf[];
    float* cs = smf;
    float* sn = smf + 512;

    const int tid = threadIdx.x;
    const int hg  = tid >> 6;
    const int t   = tid & 63;

    float* sq = smf + 1024 + hg * GRP_WORDS;
    float* sk = sq + WIN * QS;
    float* sv = sk + WIN * QS;
    float* sp = sv + WIN * QS;

    const int w = blockIdx.x;

    for (int e = tid; e < 512; e += 256)
        sincosf(rope[e], &sn[e], &cs[e]);
    __syncthreads();

    const int sr = t >> 2, qt = t & 3;
    const int lane = tid & 31;
    const int c  = lane & 15;
    const int rq = (lane >> 4) + 2 * ((t >> 5) & 1);

    for (int it = 0; it < 4; ++it) {
        const int h = hg * 4 + it;

        {
            const size_t base = ((size_t)(w * WIN + sr)) * DIM + h * HD;
            const int d0 = qt * 8;

            float4 qa0 = *(const float4*)(g_q + base + d0);
            float4 qa1 = *(const float4*)(g_q + base + d0 + 4);
            float4 qb0 = *(const float4*)(g_q + base + d0 + 32);
            float4 qb1 = *(const float4*)(g_q + base + d0 + 36);
            float4 ka0 = *(const float4*)(g_k + base + d0);
            float4 ka1 = *(const float4*)(g_k + base + d0 + 4);
            float4 kb0 = *(const float4*)(g_k + base + d0 + 32);
            float4 kb1 = *(const float4*)(g_k + base + d0 + 36);

            float qa[8] = {qa0.x,qa0.y,qa0.z,qa0.w, qa1.x,qa1.y,qa1.z,qa1.w};
            float qb[8] = {qb0.x,qb0.y,qb0.z,qb0.w, qb1.x,qb1.y,qb1.z,qb1.w};
            float ka[8] = {ka0.x,ka0.y,ka0.z,ka0.w, ka1.x,ka1.y,ka1.z,ka1.w};
            float kb[8] = {kb0.x,kb0.y,kb0.z,kb0.w, kb1.x,kb1.y,kb1.z,kb1.w};

            float qlo[8], qhi[8], klo[8], khi[8];
            #pragma unroll
            for (int j = 0; j < 8; j++) {
                const float C_ = cs[sr * 32 + d0 + j];
                const float S_ = sn[sr * 32 + d0 + j];
                qlo[j] = qa[j] * C_ - qb[j] * S_;
                qhi[j] = qa[j] * S_ + qb[j] * C_;
                klo[j] = ka[j] * C_ - kb[j] * S_;
                khi[j] = ka[j] * S_ + kb[j] * C_;
            }
            float* qrow = sq + sr * QS;
            float* krow = sk + sr * QS;
            *(float4*)(qrow + d0)      = make_float4(qlo[0],qlo[1],qlo[2],qlo[3]);
            *(float4*)(qrow + d0 + 4)  = make_float4(qlo[4],qlo[5],qlo[6],qlo[7]);
            *(float4*)(qrow + d0 + 32) = make_float4(qhi[0],qhi[1],qhi[2],qhi[3]);
            *(float4*)(qrow + d0 + 36) = make_float4(qhi[4],qhi[5],qhi[6],qhi[7]);
            *(float4*)(krow + d0)      = make_float4(klo[0],klo[1],klo[2],klo[3]);
            *(float4*)(krow + d0 + 4)  = make_float4(klo[4],klo[5],klo[6],klo[7]);
            *(float4*)(krow + d0 + 32) = make_float4(khi[0],khi[1],khi[2],khi[3]);
            *(float4*)(krow + d0 + 36) = make_float4(khi[4],khi[5],khi[6],khi[7]);

            const int dv = qt * 16;
            float* vrow = sv + sr * QS;
            #pragma unroll
            for (int i = 0; i < 4; i++)
                *(float4*)(vrow + dv + 4 * i) = *(const float4*)(g_v + base + dv + 4 * i);
        }
        __syncthreads();

        float s0 = 0.f, s1 = 0.f, s2 = 0.f, s3 = 0.f;
        {
            const float* krow = sk + c * QS;
            const float* q0r = sq + rq * QS;
            const float* q1r = q0r + 4 * QS;
            const float* q2r = q0r + 8 * QS;
            const float* q3r = q0r + 12 * QS;
            #pragma unroll
            for (int j = 0; j < 16; j++) {
                float4 kf = *(const float4*)(krow + 4 * j);
                float4 q0 = *(const float4*)(q0r + 4 * j);
                float4 q1 = *(const float4*)(q1r + 4 * j);
                float4 q2 = *(const float4*)(q2r + 4 * j);
                float4 q3 = *(const float4*)(q3r + 4 * j);
                s0 = fmaf(q0.x,kf.x,fmaf(q0.y,kf.y,fmaf(q0.z,kf.z,fmaf(q0.w,kf.w,s0))));
                s1 = fmaf(q1.x,kf.x,fmaf(q1.y,kf.y,fmaf(q1.z,kf.z,fmaf(q1.w,kf.w,s1))));
                s2 = fmaf(q2.x,kf.x,fmaf(q2.y,kf.y,fmaf(q2.z,kf.z,fmaf(q2.w,kf.w,s2))));
                s3 = fmaf(q3.x,kf.x,fmaf(q3.y,kf.y,fmaf(q3.z,kf.z,fmaf(q3.w,kf.w,s3))));
            }
        }
        s0 *= 0.125f; s1 *= 0.125f; s2 *= 0.125f; s3 *= 0.125f;

        float m0 = s0, m1 = s1, m2 = s2, m3 = s3;
        #pragma unroll
        for (int o = 8; o; o >>= 1) {
            m0 = fmaxf(m0, __shfl_xor_sync(0xffffffffu, m0, o));
            m1 = fmaxf(m1, __shfl_xor_sync(0xffffffffu, m1, o));
            m2 = fmaxf(m2, __shfl_xor_sync(0xffffffffu, m2, o));
            m3 = fmaxf(m3, __shfl_xor_sync(0xffffffffu, m3, o));
        }
        float e0 = expf(s0 - m0), e1 = expf(s1 - m1), e2 = expf(s2 - m2), e3 = expf(s3 - m3);
        float u0 = e0, u1 = e1, u2 = e2, u3 = e3;
        #pragma unroll
        for (int o = 8; o; o >>= 1) {
            u0 += __shfl_xor_sync(0xffffffffu, u0, o);
            u1 += __shfl_xor_sync(0xffffffffu, u1, o);
            u2 += __shfl_xor_sync(0xffffffffu, u2, o);
            u3 += __shfl_xor_sync(0xffffffffu, u3, o);
        }
        sp[(rq)      * PS + c] = e0 / u0;
        sp[(rq + 4)  * PS + c] = e1 / u1;
        sp[(rq + 8)  * PS + c] = e2 / u2;
        sp[(rq + 12) * PS + c] = e3 / u3;
        __syncwarp();

        float4 o0 = {0,0,0,0}, o1 = {0,0,0,0}, o2 = {0,0,0,0}, o3 = {0,0,0,0};
        #pragma unroll
        for (int kc = 0; kc < 4; kc++) {
            float4 p0 = *(const float4*)(sp + (rq)      * PS + 4 * kc);
            float4 p1 = *(const float4*)(sp + (rq + 4)  * PS + 4 * kc);
            float4 p2 = *(const float4*)(sp + (rq + 8)  * PS + 4 * kc);
            float4 p3 = *(const float4*)(sp + (rq + 12) * PS + 4 * kc);
            const float pa0[4] = {p0.x,p0.y,p0.z,p0.w};
            const float pa1[4] = {p1.x,p1.y,p1.z,p1.w};
            const float pa2[4] = {p2.x,p2.y,p2.z,p2.w};
            const float pa3[4] = {p3.x,p3.y,p3.z,p3.w};
            #pragma unroll
            for (int jj = 0; jj < 4; jj++) {
                float4 vf = *(const float4*)(sv + (4 * kc + jj) * QS + 4 * c);
                o0.x = fmaf(pa0[jj], vf.x, o0.x); o0.y = fmaf(pa0[jj], vf.y, o0.y);
                o0.z = fmaf(pa0[jj], vf.z, o0.z); o0.w = fmaf(pa0[jj], vf.w, o0.w);
                o1.x = fmaf(pa1[jj], vf.x, o1.x); o1.y = fmaf(pa1[jj], vf.y, o1.y);
                o1.z = fmaf(pa1[jj], vf.z, o1.z); o1.w = fmaf(pa1[jj], vf.w, o1.w);
                o2.x = fmaf(pa2[jj], vf.x, o2.x); o2.y = fmaf(pa2[jj], vf.y, o2.y);
                o2.z = fmaf(pa2[jj], vf.z, o2.z); o2.w = fmaf(pa2[jj], vf.w, o2.w);
                o3.x = fmaf(pa3[jj], vf.x, o3.x); o3.y = fmaf(pa3[jj], vf.y, o3.y);
                o3.z = fmaf(pa3[jj], vf.z, o3.z); o3.w = fmaf(pa3[jj], vf.w, o3.w);
            }
        }
        {
            const size_t ob = ((size_t)(w * WIN)) * DIM + h * HD + 4 * c;
            auto sth = [](size_t idx, float4 o) {
                __half2 lo = __floats2half2_rn(o.x, o.y);
                __half2 hi = __floats2half2_rn(o.z, o.w);
                *(uint2*)(g_attnh + idx) = make_uint2(*(uint32_t*)&lo, *(uint32_t*)&hi);
            };
            sth(ob + (size_t)(rq)      * DIM, o0);
            sth(ob + (size_t)(rq + 4)  * DIM, o1);
            sth(ob + (size_t)(rq + 8)  * DIM, o2);
            sth(ob + (size_t)(rq + 12) * DIM, o3);
        }
        __syncthreads();
    }
}

// ---------------------------------------------------------------------------
extern "C" void kernel_launch(void* const* d_in, const int* in_sizes, int n_in,
                              void* d_out, int out_size)
{
    const float* x    = (const float*)d_in[0];
    const float* rope = (const float*)d_in[1];
    const float* wq   = (const float*)d_in[2];
    const float* wk   = (const float*)d_in[3];
    const float* wv   = (const float*)d_in[4];
    const float* wo   = (const float*)d_in[5];
    float* out        = (float*)d_out;

    float *q, *k, *v;
    __half *xh;
    cudaGetSymbolAddress((void**)&q,  g_q);
    cudaGetSymbolAddress((void**)&k,  g_k);
    cudaGetSymbolAddress((void**)&v,  g_v);
    cudaGetSymbolAddress((void**)&xh, g_xh);

    cudaFuncSetAttribute(gemm_qkv, cudaFuncAttributeMaxDynamicSharedMemorySize, GSMEM);
    cudaFuncSetAttribute(gemm_wo,  cudaFuncAttributeMaxDynamicSharedMemorySize, GSMEM);
    cudaFuncSetAttribute(attn_kernel, cudaFuncAttributeMaxDynamicSharedMemorySize,
                         ATTN_SMEM_WORDS * 4);

    // fp32 -> fp16 prepass
    f2h<<<1024, 256>>>((const float4*)x, (uint2*)xh, NTOK * DIM / 4);
    dim3 wgrid(128, 1, 4);
    f2h_w<<<wgrid, 256>>>((const float4*)wq, (const float4*)wk,
                          (const float4*)wv, (const float4*)wo);

    dim3 grid_qkv(DIM / BN, NTOK / BM, 3);   // (8, 64, 3)
    gemm_qkv<<<grid_qkv, 256, GSMEM>>>(xh, q, k, v);

    attn_kernel<<<NWIN, 256, ATTN_SMEM_WORDS * 4>>>(rope);

    dim3 grid(DIM / BN, NTOK / BM);          // (8, 64)
    gemm_wo<<<grid, 256, GSMEM>>>(out);
}

// round 7
// speedup vs baseline: 5.2710x; 1.0116x over previous
#include <cuda_runtime.h>
#include <cuda_fp16.h>
#include <cstdint>
#include <math.h>

#define DIM    1024
#define HEADS  16
#define HD     64
#define WIN    16
#define NTOK   16384   // B*S
#define NWIN   1024

// Scratch (allocation-free rule: __device__ globals)
__device__ __align__(16) __half g_qh[NTOK * DIM];
__device__ __align__(16) __half g_kh[NTOK * DIM];
__device__ __align__(16) __half g_vh[NTOK * DIM];
__device__ __align__(16) __half g_attnh[NTOK * DIM];
__device__ __align__(16) __half g_xh[NTOK * DIM];
__device__ __align__(16) __half g_wqh[DIM * DIM];
__device__ __align__(16) __half g_wkh[DIM * DIM];
__device__ __align__(16) __half g_wvh[DIM * DIM];
__device__ __align__(16) __half g_woh[DIM * DIM];

// ---------------------------------------------------------------------------
// helpers
// ---------------------------------------------------------------------------
__device__ __forceinline__ uint32_t smem_u32(const void* p) {
    uint32_t a;
    asm("{ .reg .u64 t; cvta.to.shared.u64 t, %1; cvt.u32.u64 %0, t; }"
        : "=r"(a) : "l"(p));
    return a;
}
__device__ __forceinline__ void cp_async16(uint32_t dst, const void* src) {
    asm volatile("cp.async.cg.shared.global [%0], [%1], 16;"
                 :: "r"(dst), "l"(src) : "memory");
}
__device__ __forceinline__ void cp_commit() {
    asm volatile("cp.async.commit_group;" ::: "memory");
}
template <int N>
__device__ __forceinline__ void cp_wait() {
    asm volatile("cp.async.wait_group %0;" :: "n"(N) : "memory");
}
__device__ __forceinline__ void ldsm_x4(uint32_t r[4], uint32_t addr) {
    asm volatile("ldmatrix.sync.aligned.m8n8.x4.shared.b16 {%0,%1,%2,%3}, [%4];"
                 : "=r"(r[0]), "=r"(r[1]), "=r"(r[2]), "=r"(r[3]) : "r"(addr));
}
__device__ __forceinline__ void mma_f16_16x8x16(float c[4],
                                                uint32_t a0, uint32_t a1,
                                                uint32_t a2, uint32_t a3,
                                                uint32_t b0, uint32_t b1) {
    asm volatile(
        "mma.sync.aligned.m16n8k16.row.col.f32.f16.f16.f32 "
        "{%0,%1,%2,%3}, {%4,%5,%6,%7}, {%8,%9}, {%0,%1,%2,%3};"
        : "+f"(c[0]), "+f"(c[1]), "+f"(c[2]), "+f"(c[3])
        : "r"(a0), "r"(a1), "r"(a2), "r"(a3), "r"(b0), "r"(b1));
}
// unpack 8 halves (uint4) -> 8 floats
__device__ __forceinline__ void h8f(const uint4 u, float f[8]) {
    float2 a = __half22float2(*(const __half2*)&u.x);
    float2 b = __half22float2(*(const __half2*)&u.y);
    float2 c = __half22float2(*(const __half2*)&u.z);
    float2 d = __half22float2(*(const __half2*)&u.w);
    f[0]=a.x; f[1]=a.y; f[2]=b.x; f[3]=b.y; f[4]=c.x; f[5]=c.y; f[6]=d.x; f[7]=d.y;
}

// ---------------------------------------------------------------------------
// fp16 mma.sync GEMM: C[M,N] = A[M,K]*B[N,K]^T, fp32 accum.
// CTA 256x128, BK=64, 256 threads = 8 warps of 64x64.
// 3-stage cp.async pipeline, ldmatrix fragments, 144B smem row stride.
// ---------------------------------------------------------------------------
constexpr int BM = 256, BN = 128, BK = 64;
constexpr int ROWB   = 144;
constexpr int A_SZ   = BM * ROWB;
constexpr int B_SZ   = BN * ROWB;
constexpr int STG_SZ = A_SZ + B_SZ;
constexpr int NSTG   = 3;
constexpr int GSMEM  = NSTG * STG_SZ;       // 165888

template <bool HALF_OUT>
__device__ __forceinline__
void gemm_body(const __half* __restrict__ A, const __half* __restrict__ B,
               void* __restrict__ Cout)
{
    extern __shared__ uint32_t sm[];
    const uint32_t sbu = smem_u32(sm);

    const int tid  = threadIdx.x;
    const int lane = tid & 31, wid = tid >> 5;
    const int g = lane >> 2, tid4 = lane & 3;
    const int warpM = wid >> 1;
    const int warpN = wid & 1;
    const int bm = blockIdx.y * BM, bn = blockIdx.x * BN;

    const int arow = tid >> 3, acc8 = tid & 7;
    const __half* Ag = A + (size_t)(bm + arow) * DIM + acc8 * 8;
    const __half* Bg = B + (size_t)(bn + arow) * DIM + acc8 * 8;
    const uint32_t sdA = sbu + arow * ROWB + acc8 * 16;
    const uint32_t sdB = sbu + A_SZ + arow * ROWB + acc8 * 16;

    auto stage = [&](int s, int kt) {
        const uint32_t so = s * STG_SZ;
        const size_t ko = (size_t)kt * BK;
        #pragma unroll
        for (int i = 0; i < 8; i++)
            cp_async16(sdA + so + i * 32 * ROWB, Ag + ko + (size_t)(32 * i) * DIM);
        #pragma unroll
        for (int i = 0; i < 4; i++)
            cp_async16(sdB + so + i * 32 * ROWB, Bg + ko + (size_t)(32 * i) * DIM);
    };

    const uint32_t aoff = (warpM * 64 + (lane & 15)) * ROWB + ((lane >> 4) << 4);
    const uint32_t boff = A_SZ + (warpN * 64 + (lane & 15)) * ROWB + ((lane >> 4) << 4);

    float acc[4][8][4];
    #pragma unroll
    for (int i = 0; i < 4; i++)
        #pragma unroll
        for (int j = 0; j < 8; j++)
            #pragma unroll
            for (int q = 0; q < 4; q++)
                acc[i][j][q] = 0.f;

    stage(0, 0); cp_commit();
    stage(1, 1); cp_commit();

    const int NKT = DIM / BK;   // 16
    int s = 0;
    for (int kt = 0; kt < NKT; kt++) {
        cp_wait<1>();
        __syncthreads();

        if (kt + 2 < NKT) stage((s + 2) % NSTG, kt + 2);
        cp_commit();

        const uint32_t ab = sbu + s * STG_SZ + aoff;
        const uint32_t bb = sbu + s * STG_SZ + boff;

        #pragma unroll
        for (int ks = 0; ks < 4; ks++) {
            uint32_t af[4][4], bf[2][4];
            #pragma unroll
            for (int mt = 0; mt < 4; mt++)
                ldsm_x4(af[mt], ab + mt * 16 * ROWB + ks * 32);
            #pragma unroll
            for (int p = 0; p < 2; p++)
                ldsm_x4(bf[p], bb + p * 16 * ROWB + ks * 32);
            #pragma unroll
            for (int mt = 0; mt < 4; mt++)
                #pragma unroll
                for (int p = 0; p < 2; p++) {
                    mma_f16_16x8x16(acc[mt][4 * p],
                                    af[mt][0], af[mt][1], af[mt][2], af[mt][3],
                                    bf[p][0], bf[p][2]);
                    mma_f16_16x8x16(acc[mt][4 * p + 1],
                                    af[mt][0], af[mt][1], af[mt][2], af[mt][3],
                                    bf[p][1], bf[p][3]);
                }
            uint32_t bg[2][4];
            #pragma unroll
            for (int p = 0; p < 2; p++)
                ldsm_x4(bg[p], bb + (2 + p) * 16 * ROWB + ks * 32);
            #pragma unroll
            for (int mt = 0; mt < 4; mt++)
                #pragma unroll
                for (int p = 0; p < 2; p++) {
                    mma_f16_16x8x16(acc[mt][4 * p + 2],
                                    af[mt][0], af[mt][1], af[mt][2], af[mt][3],
                                    bg[p][0], bg[p][2]);
                    mma_f16_16x8x16(acc[mt][4 * p + 3],
                                    af[mt][0], af[mt][1], af[mt][2], af[mt][3],
                                    bg[p][1], bg[p][3]);
                }
        }
        s = (s + 1) % NSTG;
    }

    #pragma unroll
    for (int mt = 0; mt < 4; mt++) {
        const int r0 = bm + warpM * 64 + mt * 16 + g;
        #pragma unroll
        for (int p = 0; p < 2; p++)
            #pragma unroll
            for (int q = 0; q < 4; q++) {
                const int ncol = bn + warpN * 64 + p * 16 + (q & 1) * 8 + (q >> 1) * 32;
                const float* a = acc[mt][4 * p + q];
                if (HALF_OUT) {
                    __half* Ch = (__half*)Cout;
                    *(__half2*)(Ch + (size_t)r0 * DIM + ncol + 2 * tid4) =
                        __floats2half2_rn(a[0], a[1]);
                    *(__half2*)(Ch + (size_t)(r0 + 8) * DIM + ncol + 2 * tid4) =
                        __floats2half2_rn(a[2], a[3]);
                } else {
                    float* Cf = (float*)Cout;
                    *(float2*)(Cf + (size_t)r0 * DIM + ncol + 2 * tid4) =
                        make_float2(a[0], a[1]);
                    *(float2*)(Cf + (size_t)(r0 + 8) * DIM + ncol + 2 * tid4) =
                        make_float2(a[2], a[3]);
                }
            }
    }
}

__global__ __launch_bounds__(256, 1)
void gemm_qkv(const __half* __restrict__ A)
{
    const int z = blockIdx.z;
    const __half* B = (z == 0) ? g_wqh : (z == 1) ? g_wkh : g_wvh;
    __half* C       = (z == 0) ? g_qh : (z == 1) ? g_kh : g_vh;
    gemm_body<true>(A, B, C);
}

__global__ __launch_bounds__(256, 1)
void gemm_wo(float* __restrict__ C)
{
    gemm_body<false>(g_attnh, g_woh, C);
}

// ---------------------------------------------------------------------------
// fp32 -> fp16 conversion prepass
// ---------------------------------------------------------------------------
__global__ void f2h(const float4* __restrict__ src, uint2* __restrict__ dst, int n4)
{
    int i = blockIdx.x * blockDim.x + threadIdx.x;
    const int stride = gridDim.x * blockDim.x;
    for (; i < n4; i += stride) {
        float4 v = src[i];
        __half2 lo = __floats2half2_rn(v.x, v.y);
        __half2 hi = __floats2half2_rn(v.z, v.w);
        dst[i] = make_uint2(*(uint32_t*)&lo, *(uint32_t*)&hi);
    }
}

__global__ void f2h_w(const float4* __restrict__ w0, const float4* __restrict__ w1,
                      const float4* __restrict__ w2, const float4* __restrict__ w3)
{
    const int z = blockIdx.z;
    const float4* src = (z == 0) ? w0 : (z == 1) ? w1 : (z == 2) ? w2 : w3;
    uint2* dst = (uint2*)((z == 0) ? g_wqh : (z == 1) ? g_wkh : (z == 2) ? g_wvh : g_woh);
    const int n4 = DIM * DIM / 4;
    int i = blockIdx.x * blockDim.x + threadIdx.x;
    const int stride = gridDim.x * blockDim.x;
    for (; i < n4; i += stride) {
        float4 v = src[i];
        __half2 lo = __floats2half2_rn(v.x, v.y);
        __half2 hi = __floats2half2_rn(v.z, v.w);
        dst[i] = make_uint2(*(uint32_t*)&lo, *(uint32_t*)&hi);
    }
}

// ---------------------------------------------------------------------------
// Windowed attention, fused RoPE. fp16 q/k/v in global, fp32 compute in smem,
// fp16 output.
// ---------------------------------------------------------------------------
constexpr int QS = 68;
constexpr int PS = 20;
constexpr int GRP_WORDS = 3 * WIN * QS + WIN * PS;
constexpr int ATTN_SMEM_WORDS = 1024 + 4 * GRP_WORDS;

__global__ __launch_bounds__(256)
void attn_kernel(const float* __restrict__ rope)
{
    extern __shared__ float smf[];
    float* cs = smf;
    float* sn = smf + 512;

    const int tid = threadIdx.x;
    const int hg  = tid >> 6;
    const int t   = tid & 63;

    float* sq = smf + 1024 + hg * GRP_WORDS;
    float* sk = sq + WIN * QS;
    float* sv = sk + WIN * QS;
    float* sp = sv + WIN * QS;

    const int w = blockIdx.x;

    for (int e = tid; e < 512; e += 256)
        sincosf(rope[e], &sn[e], &cs[e]);
    __syncthreads();

    const int sr = t >> 2, qt = t & 3;
    const int lane = tid & 31;
    const int c  = lane & 15;
    const int rq = (lane >> 4) + 2 * ((t >> 5) & 1);

    for (int it = 0; it < 4; ++it) {
        const int h = hg * 4 + it;

        {
            const size_t base = ((size_t)(w * WIN + sr)) * DIM + h * HD;
            const int d0 = qt * 8;

            float qa[8], qb[8], ka[8], kb[8];
            h8f(*(const uint4*)(g_qh + base + d0),      qa);
            h8f(*(const uint4*)(g_qh + base + d0 + 32), qb);
            h8f(*(const uint4*)(g_kh + base + d0),      ka);
            h8f(*(const uint4*)(g_kh + base + d0 + 32), kb);

            float qlo[8], qhi[8], klo[8], khi[8];
            #pragma unroll
            for (int j = 0; j < 8; j++) {
                const float C_ = cs[sr * 32 + d0 + j];
                const float S_ = sn[sr * 32 + d0 + j];
                qlo[j] = qa[j] * C_ - qb[j] * S_;
                qhi[j] = qa[j] * S_ + qb[j] * C_;
                klo[j] = ka[j] * C_ - kb[j] * S_;
                khi[j] = ka[j] * S_ + kb[j] * C_;
            }
            float* qrow = sq + sr * QS;
            float* krow = sk + sr * QS;
            *(float4*)(qrow + d0)      = make_float4(qlo[0],qlo[1],qlo[2],qlo[3]);
            *(float4*)(qrow + d0 + 4)  = make_float4(qlo[4],qlo[5],qlo[6],qlo[7]);
            *(float4*)(qrow + d0 + 32) = make_float4(qhi[0],qhi[1],qhi[2],qhi[3]);
            *(float4*)(qrow + d0 + 36) = make_float4(qhi[4],qhi[5],qhi[6],qhi[7]);
            *(float4*)(krow + d0)      = make_float4(klo[0],klo[1],klo[2],klo[3]);
            *(float4*)(krow + d0 + 4)  = make_float4(klo[4],klo[5],klo[6],klo[7]);
            *(float4*)(krow + d0 + 32) = make_float4(khi[0],khi[1],khi[2],khi[3]);
            *(float4*)(krow + d0 + 36) = make_float4(khi[4],khi[5],khi[6],khi[7]);

            const int dv = qt * 16;
            float va[8], vb[8];
            h8f(*(const uint4*)(g_vh + base + dv),     va);
            h8f(*(const uint4*)(g_vh + base + dv + 8), vb);
            float* vrow = sv + sr * QS;
            *(float4*)(vrow + dv)      = make_float4(va[0],va[1],va[2],va[3]);
            *(float4*)(vrow + dv + 4)  = make_float4(va[4],va[5],va[6],va[7]);
            *(float4*)(vrow + dv + 8)  = make_float4(vb[0],vb[1],vb[2],vb[3]);
            *(float4*)(vrow + dv + 12) = make_float4(vb[4],vb[5],vb[6],vb[7]);
        }
        __syncthreads();

        float s0 = 0.f, s1 = 0.f, s2 = 0.f, s3 = 0.f;
        {
            const float* krow = sk + c * QS;
            const float* q0r = sq + rq * QS;
            const float* q1r = q0r + 4 * QS;
            const float* q2r = q0r + 8 * QS;
            const float* q3r = q0r + 12 * QS;
            #pragma unroll
            for (int j = 0; j < 16; j++) {
                float4 kf = *(const float4*)(krow + 4 * j);
                float4 q0 = *(const float4*)(q0r + 4 * j);
                float4 q1 = *(const float4*)(q1r + 4 * j);
                float4 q2 = *(const float4*)(q2r + 4 * j);
                float4 q3 = *(const float4*)(q3r + 4 * j);
                s0 = fmaf(q0.x,kf.x,fmaf(q0.y,kf.y,fmaf(q0.z,kf.z,fmaf(q0.w,kf.w,s0))));
                s1 = fmaf(q1.x,kf.x,fmaf(q1.y,kf.y,fmaf(q1.z,kf.z,fmaf(q1.w,kf.w,s1))));
                s2 = fmaf(q2.x,kf.x,fmaf(q2.y,kf.y,fmaf(q2.z,kf.z,fmaf(q2.w,kf.w,s2))));
                s3 = fmaf(q3.x,kf.x,fmaf(q3.y,kf.y,fmaf(q3.z,kf.z,fmaf(q3.w,kf.w,s3))));
            }
        }
        s0 *= 0.125f; s1 *= 0.125f; s2 *= 0.125f; s3 *= 0.125f;

        float m0 = s0, m1 = s1, m2 = s2, m3 = s3;
        #pragma unroll
        for (int o = 8; o; o >>= 1) {
            m0 = fmaxf(m0, __shfl_xor_sync(0xffffffffu, m0, o));
            m1 = fmaxf(m1, __shfl_xor_sync(0xffffffffu, m1, o));
            m2 = fmaxf(m2, __shfl_xor_sync(0xffffffffu, m2, o));
            m3 = fmaxf(m3, __shfl_xor_sync(0xffffffffu, m3, o));
        }
        float e0 = expf(s0 - m0), e1 = expf(s1 - m1), e2 = expf(s2 - m2), e3 = expf(s3 - m3);
        float u0 = e0, u1 = e1, u2 = e2, u3 = e3;
        #pragma unroll
        for (int o = 8; o; o >>= 1) {
            u0 += __shfl_xor_sync(0xffffffffu, u0, o);
            u1 += __shfl_xor_sync(0xffffffffu, u1, o);
            u2 += __shfl_xor_sync(0xffffffffu, u2, o);
            u3 += __shfl_xor_sync(0xffffffffu, u3, o);
        }
        sp[(rq)      * PS + c] = e0 / u0;
        sp[(rq + 4)  * PS + c] = e1 / u1;
        sp[(rq + 8)  * PS + c] = e2 / u2;
        sp[(rq + 12) * PS + c] = e3 / u3;
        __syncwarp();

        float4 o0 = {0,0,0,0}, o1 = {0,0,0,0}, o2 = {0,0,0,0}, o3 = {0,0,0,0};
        #pragma unroll
        for (int kc = 0; kc < 4; kc++) {
            float4 p0 = *(const float4*)(sp + (rq)      * PS + 4 * kc);
            float4 p1 = *(const float4*)(sp + (rq + 4)  * PS + 4 * kc);
            float4 p2 = *(const float4*)(sp + (rq + 8)  * PS + 4 * kc);
            float4 p3 = *(const float4*)(sp + (rq + 12) * PS + 4 * kc);
            const float pa0[4] = {p0.x,p0.y,p0.z,p0.w};
            const float pa1[4] = {p1.x,p1.y,p1.z,p1.w};
            const float pa2[4] = {p2.x,p2.y,p2.z,p2.w};
            const float pa3[4] = {p3.x,p3.y,p3.z,p3.w};
            #pragma unroll
            for (int jj = 0; jj < 4; jj++) {
                float4 vf = *(const float4*)(sv + (4 * kc + jj) * QS + 4 * c);
                o0.x = fmaf(pa0[jj], vf.x, o0.x); o0.y = fmaf(pa0[jj], vf.y, o0.y);
                o0.z = fmaf(pa0[jj], vf.z, o0.z); o0.w = fmaf(pa0[jj], vf.w, o0.w);
                o1.x = fmaf(pa1[jj], vf.x, o1.x); o1.y = fmaf(pa1[jj], vf.y, o1.y);
                o1.z = fmaf(pa1[jj], vf.z, o1.z); o1.w = fmaf(pa1[jj], vf.w, o1.w);
                o2.x = fmaf(pa2[jj], vf.x, o2.x); o2.y = fmaf(pa2[jj], vf.y, o2.y);
                o2.z = fmaf(pa2[jj], vf.z, o2.z); o2.w = fmaf(pa2[jj], vf.w, o2.w);
                o3.x = fmaf(pa3[jj], vf.x, o3.x); o3.y = fmaf(pa3[jj], vf.y, o3.y);
                o3.z = fmaf(pa3[jj], vf.z, o3.z); o3.w = fmaf(pa3[jj], vf.w, o3.w);
            }
        }
        {
            const size_t ob = ((size_t)(w * WIN)) * DIM + h * HD + 4 * c;
            auto sth = [](size_t idx, float4 o) {
                __half2 lo = __floats2half2_rn(o.x, o.y);
                __half2 hi = __floats2half2_rn(o.z, o.w);
                *(uint2*)(g_attnh + idx) = make_uint2(*(uint32_t*)&lo, *(uint32_t*)&hi);
            };
            sth(ob + (size_t)(rq)      * DIM, o0);
            sth(ob + (size_t)(rq + 4)  * DIM, o1);
            sth(ob + (size_t)(rq + 8)  * DIM, o2);
            sth(ob + (size_t)(rq + 12) * DIM, o3);
        }
        __syncthreads();
    }
}

// ---------------------------------------------------------------------------
extern "C" void kernel_launch(void* const* d_in, const int* in_sizes, int n_in,
                              void* d_out, int out_size)
{
    const float* x    = (const float*)d_in[0];
    const float* rope = (const float*)d_in[1];
    const float* wq   = (const float*)d_in[2];
    const float* wk   = (const float*)d_in[3];
    const float* wv   = (const float*)d_in[4];
    const float* wo   = (const float*)d_in[5];
    float* out        = (float*)d_out;

    __half *xh;
    cudaGetSymbolAddress((void**)&xh, g_xh);

    cudaFuncSetAttribute(gemm_qkv, cudaFuncAttributeMaxDynamicSharedMemorySize, GSMEM);
    cudaFuncSetAttribute(gemm_wo,  cudaFuncAttributeMaxDynamicSharedMemorySize, GSMEM);
    cudaFuncSetAttribute(attn_kernel, cudaFuncAttributeMaxDynamicSharedMemorySize,
                         ATTN_SMEM_WORDS * 4);

    f2h<<<1024, 256>>>((const float4*)x, (uint2*)xh, NTOK * DIM / 4);
    dim3 wgrid(128, 1, 4);
    f2h_w<<<wgrid, 256>>>((const float4*)wq, (const float4*)wk,
                          (const float4*)wv, (const float4*)wo);

    dim3 grid_qkv(DIM / BN, NTOK / BM, 3);   // (8, 64, 3)
    gemm_qkv<<<grid_qkv, 256, GSMEM>>>(xh);

    attn_kernel<<<NWIN, 256, ATTN_SMEM_WORDS * 4>>>(rope);

    dim3 grid(DIM / BN, NTOK / BM);          // (8, 64)
    gemm_wo<<<grid, 256, GSMEM>>>(out);
}

// round 8
// speedup vs baseline: 5.5770x; 1.0581x over previous
#include <cuda_runtime.h>
#include <cuda_fp16.h>
#include <cstdint>
#include <math.h>

#define DIM    1024
#define HEADS  16
#define HD     64
#define WIN    16
#define NTOK   16384   // B*S
#define NWIN   1024

// Scratch (allocation-free rule: __device__ globals)
__device__ __align__(16) __half g_qh[NTOK * DIM];
__device__ __align__(16) __half g_kh[NTOK * DIM];
__device__ __align__(16) __half g_vh[NTOK * DIM];
__device__ __align__(16) __half g_attnh[NTOK * DIM];
__device__ __align__(16) __half g_xh[NTOK * DIM];
__device__ __align__(16) __half g_wqh[DIM * DIM];
__device__ __align__(16) __half g_wkh[DIM * DIM];
__device__ __align__(16) __half g_wvh[DIM * DIM];
__device__ __align__(16) __half g_woh[DIM * DIM];

// ---------------------------------------------------------------------------
// helpers
// ---------------------------------------------------------------------------
__device__ __forceinline__ uint32_t smem_u32(const void* p) {
    uint32_t a;
    asm("{ .reg .u64 t; cvta.to.shared.u64 t, %1; cvt.u32.u64 %0, t; }"
        : "=r"(a) : "l"(p));
    return a;
}
__device__ __forceinline__ void cp_async16(uint32_t dst, const void* src) {
    asm volatile("cp.async.cg.shared.global [%0], [%1], 16;"
                 :: "r"(dst), "l"(src) : "memory");
}
__device__ __forceinline__ void cp_commit() {
    asm volatile("cp.async.commit_group;" ::: "memory");
}
template <int N>
__device__ __forceinline__ void cp_wait() {
    asm volatile("cp.async.wait_group %0;" :: "n"(N) : "memory");
}
__device__ __forceinline__ void ldsm_x4(uint32_t r[4], uint32_t addr) {
    asm volatile("ldmatrix.sync.aligned.m8n8.x4.shared.b16 {%0,%1,%2,%3}, [%4];"
                 : "=r"(r[0]), "=r"(r[1]), "=r"(r[2]), "=r"(r[3]) : "r"(addr));
}
__device__ __forceinline__ void mma_f16_16x8x16(float c[4],
                                                uint32_t a0, uint32_t a1,
                                                uint32_t a2, uint32_t a3,
                                                uint32_t b0, uint32_t b1) {
    asm volatile(
        "mma.sync.aligned.m16n8k16.row.col.f32.f16.f16.f32 "
        "{%0,%1,%2,%3}, {%4,%5,%6,%7}, {%8,%9}, {%0,%1,%2,%3};"
        : "+f"(c[0]), "+f"(c[1]), "+f"(c[2]), "+f"(c[3])
        : "r"(a0), "r"(a1), "r"(a2), "r"(a3), "r"(b0), "r"(b1));
}
// unpack 8 halves (uint4) -> 8 floats
__device__ __forceinline__ void h8f(const uint4 u, float f[8]) {
    float2 a = __half22float2(*(const __half2*)&u.x);
    float2 b = __half22float2(*(const __half2*)&u.y);
    float2 c = __half22float2(*(const __half2*)&u.z);
    float2 d = __half22float2(*(const __half2*)&u.w);
    f[0]=a.x; f[1]=a.y; f[2]=b.x; f[3]=b.y; f[4]=c.x; f[5]=c.y; f[6]=d.x; f[7]=d.y;
}
// pack 8 floats -> uint4 of halves
__device__ __forceinline__ uint4 f8h(const float f[8]) {
    __half2 a = __floats2half2_rn(f[0], f[1]);
    __half2 b = __floats2half2_rn(f[2], f[3]);
    __half2 c = __floats2half2_rn(f[4], f[5]);
    __half2 d = __floats2half2_rn(f[6], f[7]);
    return make_uint4(*(uint32_t*)&a, *(uint32_t*)&b, *(uint32_t*)&c, *(uint32_t*)&d);
}

// ---------------------------------------------------------------------------
// fp16 mma.sync GEMM: C[M,N] = A[M,K]*B[N,K]^T, fp32 accum.
// CTA 256x128, BK=64, 512 threads = 16 warps of 64x32.
// 2-stage cp.async pipeline, ldmatrix fragments, 144B smem row stride.
// ---------------------------------------------------------------------------
constexpr int BM = 256, BN = 128, BK = 64;
constexpr int ROWB   = 144;
constexpr int A_SZ   = BM * ROWB;           // 36864
constexpr int B_SZ   = BN * ROWB;           // 18432
constexpr int STG_SZ = A_SZ + B_SZ;         // 55296
constexpr int GSMEM  = 2 * STG_SZ;          // 110592
constexpr int GTHREADS = 512;

template <bool HALF_OUT>
__device__ __forceinline__
void gemm_body(const __half* __restrict__ A, const __half* __restrict__ B,
               void* __restrict__ Cout)
{
    extern __shared__ uint32_t sm[];
    const uint32_t sbu = smem_u32(sm);

    const int tid  = threadIdx.x;
    const int lane = tid & 31, wid = tid >> 5;
    const int g = lane >> 2, tid4 = lane & 3;
    const int warpM = wid & 3;                 // 0..3 -> 64 rows
    const int warpN = wid >> 2;                // 0..3 -> 32 cols
    const int bm = blockIdx.y * BM, bn = blockIdx.x * BN;

    // staging: A 2048 16B chunks (4/thread), B 1024 (2/thread)
    const int arow = tid >> 3, acc8 = tid & 7;
    const __half* Ag = A + (size_t)(bm + arow) * DIM + acc8 * 8;
    const __half* Bg = B + (size_t)(bn + arow) * DIM + acc8 * 8;
    const uint32_t sdA = sbu + arow * ROWB + acc8 * 16;
    const uint32_t sdB = sbu + A_SZ + arow * ROWB + acc8 * 16;

    auto stage = [&](int s, int kt) {
        const uint32_t so = s * STG_SZ;
        const size_t ko = (size_t)kt * BK;
        #pragma unroll
        for (int i = 0; i < 4; i++)
            cp_async16(sdA + so + i * 64 * ROWB, Ag + ko + (size_t)(64 * i) * DIM);
        #pragma unroll
        for (int i = 0; i < 2; i++)
            cp_async16(sdB + so + i * 64 * ROWB, Bg + ko + (size_t)(64 * i) * DIM);
    };

    const uint32_t aoff = (warpM * 64 + (lane & 15)) * ROWB + ((lane >> 4) << 4);
    const uint32_t boff = A_SZ + (warpN * 32 + (lane & 15)) * ROWB + ((lane >> 4) << 4);

    float acc[4][4][4];
    #pragma unroll
    for (int i = 0; i < 4; i++)
        #pragma unroll
        for (int j = 0; j < 4; j++)
            #pragma unroll
            for (int q = 0; q < 4; q++)
                acc[i][j][q] = 0.f;

    stage(0, 0); cp_commit();

    const int NKT = DIM / BK;   // 16
    int s = 0;
    for (int kt = 0; kt < NKT; kt++) {
        cp_wait<0>();
        __syncthreads();
        if (kt + 1 < NKT) { stage(s ^ 1, kt + 1); cp_commit(); }

        const uint32_t ab = sbu + s * STG_SZ + aoff;
        const uint32_t bb = sbu + s * STG_SZ + boff;

        #pragma unroll
        for (int ks = 0; ks < 4; ks++) {
            uint32_t af[4][4], bf[2][4];
            #pragma unroll
            for (int mt = 0; mt < 4; mt++)
                ldsm_x4(af[mt], ab + mt * 16 * ROWB + ks * 32);
            #pragma unroll
            for (int p = 0; p < 2; p++)
                ldsm_x4(bf[p], bb + p * 16 * ROWB + ks * 32);
            #pragma unroll
            for (int mt = 0; mt < 4; mt++)
                #pragma unroll
                for (int p = 0; p < 2; p++) {
                    mma_f16_16x8x16(acc[mt][2 * p],
                                    af[mt][0], af[mt][1], af[mt][2], af[mt][3],
                                    bf[p][0], bf[p][2]);
                    mma_f16_16x8x16(acc[mt][2 * p + 1],
                                    af[mt][0], af[mt][1], af[mt][2], af[mt][3],
                                    bf[p][1], bf[p][3]);
                }
        }
        s ^= 1;
    }

    #pragma unroll
    for (int mt = 0; mt < 4; mt++) {
        const int r0 = bm + warpM * 64 + mt * 16 + g;
        #pragma unroll
        for (int j = 0; j < 4; j++) {
            const int ncol = bn + warpN * 32 + (j >> 1) * 16 + (j & 1) * 8;
            const float* a = acc[mt][j];
            if (HALF_OUT) {
                __half* Ch = (__half*)Cout;
                *(__half2*)(Ch + (size_t)r0 * DIM + ncol + 2 * tid4) =
                    __floats2half2_rn(a[0], a[1]);
                *(__half2*)(Ch + (size_t)(r0 + 8) * DIM + ncol + 2 * tid4) =
                    __floats2half2_rn(a[2], a[3]);
            } else {
                float* Cf = (float*)Cout;
                *(float2*)(Cf + (size_t)r0 * DIM + ncol + 2 * tid4) =
                    make_float2(a[0], a[1]);
                *(float2*)(Cf + (size_t)(r0 + 8) * DIM + ncol + 2 * tid4) =
                    make_float2(a[2], a[3]);
            }
        }
    }
}

__global__ __launch_bounds__(GTHREADS, 1)
void gemm_qkv(const __half* __restrict__ A)
{
    const int z = blockIdx.z;
    const __half* B = (z == 0) ? g_wqh : (z == 1) ? g_wkh : g_wvh;
    __half* C       = (z == 0) ? g_qh : (z == 1) ? g_kh : g_vh;
    gemm_body<true>(A, B, C);
}

__global__ __launch_bounds__(GTHREADS, 1)
void gemm_wo(float* __restrict__ C)
{
    gemm_body<false>(g_attnh, g_woh, C);
}

// ---------------------------------------------------------------------------
// fp32 -> fp16 conversion prepass
// ---------------------------------------------------------------------------
__global__ void f2h(const float4* __restrict__ src, uint2* __restrict__ dst, int n4)
{
    int i = blockIdx.x * blockDim.x + threadIdx.x;
    const int stride = gridDim.x * blockDim.x;
    for (; i < n4; i += stride) {
        float4 v = src[i];
        __half2 lo = __floats2half2_rn(v.x, v.y);
        __half2 hi = __floats2half2_rn(v.z, v.w);
        dst[i] = make_uint2(*(uint32_t*)&lo, *(uint32_t*)&hi);
    }
}

__global__ void f2h_w(const float4* __restrict__ w0, const float4* __restrict__ w1,
                      const float4* __restrict__ w2, const float4* __restrict__ w3)
{
    const int z = blockIdx.z;
    const float4* src = (z == 0) ? w0 : (z == 1) ? w1 : (z == 2) ? w2 : w3;
    uint2* dst = (uint2*)((z == 0) ? g_wqh : (z == 1) ? g_wkh : (z == 2) ? g_wvh : g_woh);
    const int n4 = DIM * DIM / 4;
    int i = blockIdx.x * blockDim.x + threadIdx.x;
    const int stride = gridDim.x * blockDim.x;
    for (; i < n4; i += stride) {
        float4 v = src[i];
        __half2 lo = __floats2half2_rn(v.x, v.y);
        __half2 hi = __floats2half2_rn(v.z, v.w);
        dst[i] = make_uint2(*(uint32_t*)&lo, *(uint32_t*)&hi);
    }
}

// ---------------------------------------------------------------------------
// Windowed attention, fused RoPE. q fp32 in smem (broadcast reads), k/v fp16
// in smem, fp32 softmax, fp16 output.
// Per head-group (hg) smem block: q 4352B, k 2304B, v 2304B, sp 1280B = 10240B
// ---------------------------------------------------------------------------
constexpr int QS  = 68;    // q row stride (floats)
constexpr int KSH = 72;    // k/v row stride (halves)
constexpr int PS  = 20;    // sp row stride (floats)
constexpr int HG_BYTES = 10240;
constexpr int ATTN_SMEM = 4096 + 4 * HG_BYTES;   // 45056 B

__global__ __launch_bounds__(256)
void attn_kernel(const float* __restrict__ rope)
{
    extern __shared__ float smf[];
    float* cs = smf;
    float* sn = smf + 512;

    const int tid = threadIdx.x;
    const int hg  = tid >> 6;
    const int t   = tid & 63;

    char* gb = ((char*)smf) + 4096 + hg * HG_BYTES;
    float*  sq  = (float*)gb;
    __half* skh = (__half*)(gb + 4352);
    __half* svh = (__half*)(gb + 4352 + 2304);
    float*  sp  = (float*)(gb + 4352 + 4608);

    const int w = blockIdx.x;

    for (int e = tid; e < 512; e += 256)
        sincosf(rope[e], &sn[e], &cs[e]);
    __syncthreads();

    const int sr = t >> 2, qt = t & 3;
    const int lane = tid & 31;
    const int c  = lane & 15;
    const int rq = (lane >> 4) + 2 * ((t >> 5) & 1);

    for (int it = 0; it < 4; ++it) {
        const int h = hg * 4 + it;

        // ---- stage q (rope, fp32), k (rope, fp16), v (raw fp16 copy) ----
        {
            const size_t base = ((size_t)(w * WIN + sr)) * DIM + h * HD;
            const int d0 = qt * 8;

            float qa[8], qb[8], ka[8], kb[8];
            h8f(*(const uint4*)(g_qh + base + d0),      qa);
            h8f(*(const uint4*)(g_qh + base + d0 + 32), qb);
            h8f(*(const uint4*)(g_kh + base + d0),      ka);
            h8f(*(const uint4*)(g_kh + base + d0 + 32), kb);

            float qlo[8], qhi[8], klo[8], khi[8];
            #pragma unroll
            for (int j = 0; j < 8; j++) {
                const float C_ = cs[sr * 32 + d0 + j];
                const float S_ = sn[sr * 32 + d0 + j];
                qlo[j] = qa[j] * C_ - qb[j] * S_;
                qhi[j] = qa[j] * S_ + qb[j] * C_;
                klo[j] = ka[j] * C_ - kb[j] * S_;
                khi[j] = ka[j] * S_ + kb[j] * C_;
            }
            float* qrow = sq + sr * QS;
            *(float4*)(qrow + d0)      = make_float4(qlo[0],qlo[1],qlo[2],qlo[3]);
            *(float4*)(qrow + d0 + 4)  = make_float4(qlo[4],qlo[5],qlo[6],qlo[7]);
            *(float4*)(qrow + d0 + 32) = make_float4(qhi[0],qhi[1],qhi[2],qhi[3]);
            *(float4*)(qrow + d0 + 36) = make_float4(qhi[4],qhi[5],qhi[6],qhi[7]);

            __half* krow = skh + sr * KSH;
            *(uint4*)(krow + d0)      = f8h(klo);
            *(uint4*)(krow + d0 + 32) = f8h(khi);

            const int dv = qt * 16;
            __half* vrow = svh + sr * KSH;
            *(uint4*)(vrow + dv)     = *(const uint4*)(g_vh + base + dv);
            *(uint4*)(vrow + dv + 8) = *(const uint4*)(g_vh + base + dv + 8);
        }
        __syncthreads();

        // ---- scores: 4 q rows per thread, fp16 k unpacked ----
        float s0 = 0.f, s1 = 0.f, s2 = 0.f, s3 = 0.f;
        {
            const uint4* krow = (const uint4*)(skh + c * KSH);
            const float* q0r = sq + rq * QS;
            const float* q1r = q0r + 4 * QS;
            const float* q2r = q0r + 8 * QS;
            const float* q3r = q0r + 12 * QS;
            #pragma unroll
            for (int j = 0; j < 8; j++) {
                float kf[8];
                h8f(krow[j], kf);
                #pragma unroll
                for (int half8 = 0; half8 < 2; half8++) {
                    float4 q0 = *(const float4*)(q0r + 8 * j + 4 * half8);
                    float4 q1 = *(const float4*)(q1r + 8 * j + 4 * half8);
                    float4 q2 = *(const float4*)(q2r + 8 * j + 4 * half8);
                    float4 q3 = *(const float4*)(q3r + 8 * j + 4 * half8);
                    const float* kk = kf + 4 * half8;
                    s0 = fmaf(q0.x,kk[0],fmaf(q0.y,kk[1],fmaf(q0.z,kk[2],fmaf(q0.w,kk[3],s0))));
                    s1 = fmaf(q1.x,kk[0],fmaf(q1.y,kk[1],fmaf(q1.z,kk[2],fmaf(q1.w,kk[3],s1))));
                    s2 = fmaf(q2.x,kk[0],fmaf(q2.y,kk[1],fmaf(q2.z,kk[2],fmaf(q2.w,kk[3],s2))));
                    s3 = fmaf(q3.x,kk[0],fmaf(q3.y,kk[1],fmaf(q3.z,kk[2],fmaf(q3.w,kk[3],s3))));
                }
            }
        }
        s0 *= 0.125f; s1 *= 0.125f; s2 *= 0.125f; s3 *= 0.125f;

        float m0 = s0, m1 = s1, m2 = s2, m3 = s3;
        #pragma unroll
        for (int o = 8; o; o >>= 1) {
            m0 = fmaxf(m0, __shfl_xor_sync(0xffffffffu, m0, o));
            m1 = fmaxf(m1, __shfl_xor_sync(0xffffffffu, m1, o));
            m2 = fmaxf(m2, __shfl_xor_sync(0xffffffffu, m2, o));
            m3 = fmaxf(m3, __shfl_xor_sync(0xffffffffu, m3, o));
        }
        float e0 = expf(s0 - m0), e1 = expf(s1 - m1), e2 = expf(s2 - m2), e3 = expf(s3 - m3);
        float u0 = e0, u1 = e1, u2 = e2, u3 = e3;
        #pragma unroll
        for (int o = 8; o; o >>= 1) {
            u0 += __shfl_xor_sync(0xffffffffu, u0, o);
            u1 += __shfl_xor_sync(0xffffffffu, u1, o);
            u2 += __shfl_xor_sync(0xffffffffu, u2, o);
            u3 += __shfl_xor_sync(0xffffffffu, u3, o);
        }
        sp[(rq)      * PS + c] = e0 / u0;
        sp[(rq + 4)  * PS + c] = e1 / u1;
        sp[(rq + 8)  * PS + c] = e2 / u2;
        sp[(rq + 12) * PS + c] = e3 / u3;
        __syncwarp();

        // ---- PV: 4 rows x 4 d per thread, fp16 v unpacked ----
        float4 o0 = {0,0,0,0}, o1 = {0,0,0,0}, o2 = {0,0,0,0}, o3 = {0,0,0,0};
        #pragma unroll
        for (int kc = 0; kc < 4; kc++) {
            float4 p0 = *(const float4*)(sp + (rq)      * PS + 4 * kc);
            float4 p1 = *(const float4*)(sp + (rq + 4)  * PS + 4 * kc);
            float4 p2 = *(const float4*)(sp + (rq + 8)  * PS + 4 * kc);
            float4 p3 = *(const float4*)(sp + (rq + 12) * PS + 4 * kc);
            const float pa0[4] = {p0.x,p0.y,p0.z,p0.w};
            const float pa1[4] = {p1.x,p1.y,p1.z,p1.w};
            const float pa2[4] = {p2.x,p2.y,p2.z,p2.w};
            const float pa3[4] = {p3.x,p3.y,p3.z,p3.w};
            #pragma unroll
            for (int jj = 0; jj < 4; jj++) {
                uint2 vv = *(const uint2*)(svh + (4 * kc + jj) * KSH + 4 * c);
                float2 va = __half22float2(*(const __half2*)&vv.x);
                float2 vb = __half22float2(*(const __half2*)&vv.y);
                o0.x = fmaf(pa0[jj], va.x, o0.x); o0.y = fmaf(pa0[jj], va.y, o0.y);
                o0.z = fmaf(pa0[jj], vb.x, o0.z); o0.w = fmaf(pa0[jj], vb.y, o0.w);
                o1.x = fmaf(pa1[jj], va.x, o1.x); o1.y = fmaf(pa1[jj], va.y, o1.y);
                o1.z = fmaf(pa1[jj], vb.x, o1.z); o1.w = fmaf(pa1[jj], vb.y, o1.w);
                o2.x = fmaf(pa2[jj], va.x, o2.x); o2.y = fmaf(pa2[jj], va.y, o2.y);
                o2.z = fmaf(pa2[jj], vb.x, o2.z); o2.w = fmaf(pa2[jj], vb.y, o2.w);
                o3.x = fmaf(pa3[jj], va.x, o3.x); o3.y = fmaf(pa3[jj], va.y, o3.y);
                o3.z = fmaf(pa3[jj], vb.x, o3.z); o3.w = fmaf(pa3[jj], vb.y, o3.w);
            }
        }
        {
            const size_t ob = ((size_t)(w * WIN)) * DIM + h * HD + 4 * c;
            auto sth = [](size_t idx, float4 o) {
                __half2 lo = __floats2half2_rn(o.x, o.y);
                __half2 hi = __floats2half2_rn(o.z, o.w);
                *(uint2*)(g_attnh + idx) = make_uint2(*(uint32_t*)&lo, *(uint32_t*)&hi);
            };
            sth(ob + (size_t)(rq)      * DIM, o0);
            sth(ob + (size_t)(rq + 4)  * DIM, o1);
            sth(ob + (size_t)(rq + 8)  * DIM, o2);
            sth(ob + (size_t)(rq + 12) * DIM, o3);
        }
        __syncthreads();
    }
}

// ---------------------------------------------------------------------------
extern "C" void kernel_launch(void* const* d_in, const int* in_sizes, int n_in,
                              void* d_out, int out_size)
{
    const float* x    = (const float*)d_in[0];
    const float* rope = (const float*)d_in[1];
    const float* wq   = (const float*)d_in[2];
    const float* wk   = (const float*)d_in[3];
    const float* wv   = (const float*)d_in[4];
    const float* wo   = (const float*)d_in[5];
    float* out        = (float*)d_out;

    __half *xh;
    cudaGetSymbolAddress((void**)&xh, g_xh);

    cudaFuncSetAttribute(gemm_qkv, cudaFuncAttributeMaxDynamicSharedMemorySize, GSMEM);
    cudaFuncSetAttribute(gemm_wo,  cudaFuncAttributeMaxDynamicSharedMemorySize, GSMEM);
    cudaFuncSetAttribute(attn_kernel, cudaFuncAttributeMaxDynamicSharedMemorySize, ATTN_SMEM);

    f2h<<<1024, 256>>>((const float4*)x, (uint2*)xh, NTOK * DIM / 4);
    dim3 wgrid(128, 1, 4);
    f2h_w<<<wgrid, 256>>>((const float4*)wq, (const float4*)wk,
                          (const float4*)wv, (const float4*)wo);

    dim3 grid_qkv(DIM / BN, NTOK / BM, 3);   // (8, 64, 3)
    gemm_qkv<<<grid_qkv, GTHREADS, GSMEM>>>(xh);

    attn_kernel<<<NWIN, 256, ATTN_SMEM>>>(rope);

    dim3 grid(DIM / BN, NTOK / BM);          // (8, 64)
    gemm_wo<<<grid, GTHREADS, GSMEM>>>(out);
}

// round 9
// speedup vs baseline: 5.8822x; 1.0547x over previous
#include <cuda_runtime.h>
#include <cuda_fp16.h>
#include <cstdint>
#include <math.h>

#define DIM    1024
#define HEADS  16
#define HD     64
#define WIN    16
#define NTOK   16384   // B*S
#define NWIN   1024

// Scratch (allocation-free rule: __device__ globals)
__device__ __align__(16) __half g_attnh[NTOK * DIM];
__device__ __align__(16) __half g_xh[NTOK * DIM];
__device__ __align__(16) __half g_wqh[DIM * DIM];
__device__ __align__(16) __half g_wkh[DIM * DIM];
__device__ __align__(16) __half g_wvh[DIM * DIM];
__device__ __align__(16) __half g_woh[DIM * DIM];

// ---------------------------------------------------------------------------
// helpers
// ---------------------------------------------------------------------------
__device__ __forceinline__ uint32_t smem_u32(const void* p) {
    uint32_t a;
    asm("{ .reg .u64 t; cvta.to.shared.u64 t, %1; cvt.u32.u64 %0, t; }"
        : "=r"(a) : "l"(p));
    return a;
}
__device__ __forceinline__ void cp_async16(uint32_t dst, const void* src) {
    asm volatile("cp.async.cg.shared.global [%0], [%1], 16;"
                 :: "r"(dst), "l"(src) : "memory");
}
__device__ __forceinline__ void cp_commit() {
    asm volatile("cp.async.commit_group;" ::: "memory");
}
template <int N>
__device__ __forceinline__ void cp_wait() {
    asm volatile("cp.async.wait_group %0;" :: "n"(N) : "memory");
}
__device__ __forceinline__ void ldsm_x4(uint32_t r[4], uint32_t addr) {
    asm volatile("ldmatrix.sync.aligned.m8n8.x4.shared.b16 {%0,%1,%2,%3}, [%4];"
                 : "=r"(r[0]), "=r"(r[1]), "=r"(r[2]), "=r"(r[3]) : "r"(addr));
}
__device__ __forceinline__ void ldsm_x4_trans(uint32_t r[4], uint32_t addr) {
    asm volatile("ldmatrix.sync.aligned.m8n8.x4.trans.shared.b16 {%0,%1,%2,%3}, [%4];"
                 : "=r"(r[0]), "=r"(r[1]), "=r"(r[2]), "=r"(r[3]) : "r"(addr));
}
__device__ __forceinline__ void mma_f16_16x8x16(float c[4],
                                                uint32_t a0, uint32_t a1,
                                                uint32_t a2, uint32_t a3,
                                                uint32_t b0, uint32_t b1) {
    asm volatile(
        "mma.sync.aligned.m16n8k16.row.col.f32.f16.f16.f32 "
        "{%0,%1,%2,%3}, {%4,%5,%6,%7}, {%8,%9}, {%0,%1,%2,%3};"
        : "+f"(c[0]), "+f"(c[1]), "+f"(c[2]), "+f"(c[3])
        : "r"(a0), "r"(a1), "r"(a2), "r"(a3), "r"(b0), "r"(b1));
}
__device__ __forceinline__ void h8f(const uint4 u, float f[8]) {
    float2 a = __half22float2(*(const __half2*)&u.x);
    float2 b = __half22float2(*(const __half2*)&u.y);
    float2 c = __half22float2(*(const __half2*)&u.z);
    float2 d = __half22float2(*(const __half2*)&u.w);
    f[0]=a.x; f[1]=a.y; f[2]=b.x; f[3]=b.y; f[4]=c.x; f[5]=c.y; f[6]=d.x; f[7]=d.y;
}
__device__ __forceinline__ uint4 f8h(const float f[8]) {
    __half2 a = __floats2half2_rn(f[0], f[1]);
    __half2 b = __floats2half2_rn(f[2], f[3]);
    __half2 c = __floats2half2_rn(f[4], f[5]);
    __half2 d = __floats2half2_rn(f[6], f[7]);
    return make_uint4(*(uint32_t*)&a, *(uint32_t*)&b, *(uint32_t*)&c, *(uint32_t*)&d);
}
__device__ __forceinline__ uint32_t h2u(__half2 h) { return *(uint32_t*)&h; }

// ---------------------------------------------------------------------------
// Fused QKV GEMM + RoPE + windowed attention.
// CTA tile 128 tokens x 128 cols (= 8 windows x 2 heads). 512 threads,
// 16 warps of 32x32 GEMM tiles; attention: 1 warp per (window, head).
// ---------------------------------------------------------------------------
constexpr int FBM = 128, FBN = 128, FBK = 64;
constexpr int FROWB  = 144;                     // staging row bytes
constexpr int FA_SZ  = FBM * FROWB;             // 18432
constexpr int FB_SZ  = FBN * FROWB;             // 18432
constexpr int FSTG   = FA_SZ + FB_SZ;           // 36864
constexpr int TSTRIDE = 136;                    // tile row stride (halves)
constexpr int TILE_SZ = FBM * TSTRIDE * 2;      // 34816
constexpr int OFF_Q  = 2 * FSTG;                // 73728
constexpr int OFF_K  = OFF_Q + TILE_SZ;         // 108544
constexpr int OFF_V  = OFF_K + TILE_SZ;         // 143360
constexpr int OFF_CS = OFF_V + TILE_SZ;         // 178176
constexpr int OFF_SN = OFF_CS + 2048;
constexpr int FSMEM  = OFF_SN + 2048;           // 182272

__global__ __launch_bounds__(512, 1)
void fused_qkv_attn(const float* __restrict__ rope)
{
    extern __shared__ char smc[];
    const uint32_t sb = smem_u32(smc);
    float* cs = (float*)(smc + OFF_CS);
    float* sn = (float*)(smc + OFF_SN);

    const int tid  = threadIdx.x;
    const int lane = tid & 31, wid = tid >> 5;
    const int g = lane >> 2, tid4 = lane & 3;
    const int warpM = wid & 3, warpN = wid >> 2;
    const int bm = blockIdx.y * FBM, bn = blockIdx.x * FBN;

    if (tid < 512) sincosf(rope[tid], &sn[tid], &cs[tid]);

    // staging mapping: rows srow, srow+64; chunk acc8 (8 halves)
    const int srow = tid >> 3, acc8 = tid & 7;
    const __half* Ag = g_xh + (size_t)(bm + srow) * DIM + acc8 * 8;
    const uint32_t sdA = sb + srow * FROWB + acc8 * 16;
    const uint32_t sdB = sb + FA_SZ + srow * FROWB + acc8 * 16;

    auto stage = [&](int s, int kt, const __half* Bw) {
        const uint32_t so = s * FSTG;
        const size_t ko = (size_t)kt * FBK;
        cp_async16(sdA + so,              Ag + ko);
        cp_async16(sdA + so + 64 * FROWB, Ag + ko + (size_t)64 * DIM);
        const __half* Bg = Bw + (size_t)(bn + srow) * DIM + acc8 * 8;
        cp_async16(sdB + so,              Bg + ko);
        cp_async16(sdB + so + 64 * FROWB, Bg + ko + (size_t)64 * DIM);
    };

    const uint32_t aoff = (warpM * 32 + (lane & 15)) * FROWB + ((lane >> 4) << 4);
    const uint32_t boff = FA_SZ + (warpN * 32 + (lane & 15)) * FROWB + ((lane >> 4) << 4);

    // ---- 3 GEMM phases: q, k, v ----
    #pragma unroll 1
    for (int ph = 0; ph < 3; ph++) {
        const __half* Bw = (ph == 0) ? g_wqh : (ph == 1) ? g_wkh : g_wvh;

        float acc[2][4][4];
        #pragma unroll
        for (int i = 0; i < 2; i++)
            #pragma unroll
            for (int j = 0; j < 4; j++)
                #pragma unroll
                for (int q = 0; q < 4; q++)
                    acc[i][j][q] = 0.f;

        stage(0, 0, Bw); cp_commit();
        int s = 0;
        #pragma unroll 1
        for (int kt = 0; kt < DIM / FBK; kt++) {
            cp_wait<0>();
            __syncthreads();
            if (kt + 1 < DIM / FBK) { stage(s ^ 1, kt + 1, Bw); cp_commit(); }

            const uint32_t ab = sb + s * FSTG + aoff;
            const uint32_t bb = sb + s * FSTG + boff;
            #pragma unroll
            for (int ks = 0; ks < 4; ks++) {
                uint32_t af[2][4], bf[2][4];
                ldsm_x4(af[0], ab + ks * 32);
                ldsm_x4(af[1], ab + 16 * FROWB + ks * 32);
                ldsm_x4(bf[0], bb + ks * 32);
                ldsm_x4(bf[1], bb + 16 * FROWB + ks * 32);
                #pragma unroll
                for (int mt = 0; mt < 2; mt++)
                    #pragma unroll
                    for (int p = 0; p < 2; p++) {
                        mma_f16_16x8x16(acc[mt][2 * p],
                                        af[mt][0], af[mt][1], af[mt][2], af[mt][3],
                                        bf[p][0], bf[p][2]);
                        mma_f16_16x8x16(acc[mt][2 * p + 1],
                                        af[mt][0], af[mt][1], af[mt][2], af[mt][3],
                                        bf[p][1], bf[p][3]);
                    }
            }
            s ^= 1;
        }

        // epilogue: acc -> fp16 smem tile
        __half* tp = (__half*)(smc + OFF_Q + ph * TILE_SZ);
        #pragma unroll
        for (int mt = 0; mt < 2; mt++) {
            const int r0 = warpM * 32 + mt * 16 + g;
            #pragma unroll
            for (int j = 0; j < 4; j++) {
                const int ncol = warpN * 32 + (j >> 1) * 16 + (j & 1) * 8 + 2 * tid4;
                *(__half2*)(tp + r0 * TSTRIDE + ncol) =
                    __floats2half2_rn(acc[mt][j][0], acc[mt][j][1]);
                *(__half2*)(tp + (r0 + 8) * TSTRIDE + ncol) =
                    __floats2half2_rn(acc[mt][j][2], acc[mt][j][3]);
            }
        }
    }
    __syncthreads();

    // ---- RoPE in-place on q and k tiles ----
    {
        const int t  = tid >> 2;            // token row 0..127
        const int jq = (tid & 3) * 8;       // freq start
        const int pos = t & 15;
        #pragma unroll
        for (int tl = 0; tl < 2; tl++) {
            __half* tb = (__half*)(smc + (tl ? OFF_K : OFF_Q));
            #pragma unroll
            for (int h = 0; h < 2; h++) {
                __half* row = tb + t * TSTRIDE + h * 64;
                float lo[8], hi[8], nl[8], nh[8];
                h8f(*(uint4*)(row + jq), lo);
                h8f(*(uint4*)(row + 32 + jq), hi);
                #pragma unroll
                for (int j = 0; j < 8; j++) {
                    const float C_ = cs[pos * 32 + jq + j];
                    const float S_ = sn[pos * 32 + jq + j];
                    nl[j] = lo[j] * C_ - hi[j] * S_;
                    nh[j] = lo[j] * S_ + hi[j] * C_;
                }
                *(uint4*)(row + jq)      = f8h(nl);
                *(uint4*)(row + 32 + jq) = f8h(nh);
            }
        }
    }
    __syncthreads();

    // ---- attention: 1 warp per (window, head) ----
    {
        const int wi = wid & 7, head = wid >> 3;
        const int r16 = lane & 15, hc = (lane >> 4) * 8;
        const uint32_t base = sb + ((uint32_t)((wi * 16 + r16) * TSTRIDE + head * 64 + hc) << 1);
        const uint32_t qb = base + OFF_Q;
        const uint32_t kb = base + OFF_K;
        const uint32_t vb = base + OFF_V;

        // scores S = q . k^T  (16x16), fp32 accum
        float sc[2][4] = {};
        #pragma unroll
        for (int ks = 0; ks < 4; ks++) {
            uint32_t aq[4], bk[4];
            ldsm_x4(aq, qb + ks * 32);
            ldsm_x4(bk, kb + ks * 32);
            mma_f16_16x8x16(sc[0], aq[0], aq[1], aq[2], aq[3], bk[0], bk[2]);
            mma_f16_16x8x16(sc[1], aq[0], aq[1], aq[2], aq[3], bk[1], bk[3]);
        }
        #pragma unroll
        for (int t2 = 0; t2 < 2; t2++)
            #pragma unroll
            for (int q = 0; q < 4; q++)
                sc[t2][q] *= 0.125f;

        // softmax: row g -> {sc[0][0],sc[0][1],sc[1][0],sc[1][1]} x4 lanes (tid4)
        //          row g+8 -> {sc[0][2],sc[0][3],sc[1][2],sc[1][3]}
        float mA = fmaxf(fmaxf(sc[0][0], sc[0][1]), fmaxf(sc[1][0], sc[1][1]));
        float mB = fmaxf(fmaxf(sc[0][2], sc[0][3]), fmaxf(sc[1][2], sc[1][3]));
        mA = fmaxf(mA, __shfl_xor_sync(0xffffffffu, mA, 1));
        mA = fmaxf(mA, __shfl_xor_sync(0xffffffffu, mA, 2));
        mB = fmaxf(mB, __shfl_xor_sync(0xffffffffu, mB, 1));
        mB = fmaxf(mB, __shfl_xor_sync(0xffffffffu, mB, 2));
        float eA0 = expf(sc[0][0] - mA), eA1 = expf(sc[0][1] - mA);
        float eA2 = expf(sc[1][0] - mA), eA3 = expf(sc[1][1] - mA);
        float eB0 = expf(sc[0][2] - mB), eB1 = expf(sc[0][3] - mB);
        float eB2 = expf(sc[1][2] - mB), eB3 = expf(sc[1][3] - mB);
        float sA = eA0 + eA1 + eA2 + eA3;
        float sB = eB0 + eB1 + eB2 + eB3;
        sA += __shfl_xor_sync(0xffffffffu, sA, 1);
        sA += __shfl_xor_sync(0xffffffffu, sA, 2);
        sB += __shfl_xor_sync(0xffffffffu, sB, 1);
        sB += __shfl_xor_sync(0xffffffffu, sB, 2);
        const float iA = 1.f / sA, iB = 1.f / sB;

        // pack P into A-fragment (m16 k16): a0=(g,k0-7) a1=(g+8,k0-7) a2=(g,k8-15) a3=(g+8,k8-15)
        const uint32_t p0 = h2u(__floats2half2_rn(eA0 * iA, eA1 * iA));
        const uint32_t p1 = h2u(__floats2half2_rn(eB0 * iB, eB1 * iB));
        const uint32_t p2 = h2u(__floats2half2_rn(eA2 * iA, eA3 * iA));
        const uint32_t p3 = h2u(__floats2half2_rn(eB2 * iB, eB3 * iB));

        // PV: V fragments via ldmatrix.trans ([token][dim] -> B n8k16)
        float o[8][4] = {};
        #pragma unroll
        for (int nt = 0; nt < 4; nt++) {
            uint32_t bv[4];
            ldsm_x4_trans(bv, vb + nt * 32);
            mma_f16_16x8x16(o[2 * nt],     p0, p1, p2, p3, bv[0], bv[1]);
            mma_f16_16x8x16(o[2 * nt + 1], p0, p1, p2, p3, bv[2], bv[3]);
        }

        // store output (fp16)
        const size_t orow = (size_t)(bm + wi * 16 + g);
        const int col0 = bn + head * 64;
        #pragma unroll
        for (int nt = 0; nt < 4; nt++)
            #pragma unroll
            for (int sub = 0; sub < 2; sub++) {
                const int j = 2 * nt + sub;
                const int col = col0 + nt * 16 + sub * 8 + 2 * tid4;
                *(__half2*)(g_attnh + orow * DIM + col) =
                    __floats2half2_rn(o[j][0], o[j][1]);
                *(__half2*)(g_attnh + (orow + 8) * DIM + col) =
                    __floats2half2_rn(o[j][2], o[j][3]);
            }
    }
}

// ---------------------------------------------------------------------------
// WO GEMM (R8 structure): CTA 256x128, BK=64, 512 threads, 16 warps of 64x32.
// ---------------------------------------------------------------------------
constexpr int BM = 256, BN = 128, BK = 64;
constexpr int ROWB   = 144;
constexpr int A_SZ   = BM * ROWB;
constexpr int B_SZ   = BN * ROWB;
constexpr int STG_SZ = A_SZ + B_SZ;
constexpr int GSMEM  = 2 * STG_SZ;          // 110592

__global__ __launch_bounds__(512, 1)
void gemm_wo(float* __restrict__ Cout)
{
    extern __shared__ uint32_t sm[];
    const uint32_t sbu = smem_u32(sm);
    const __half* A = g_attnh;
    const __half* B = g_woh;

    const int tid  = threadIdx.x;
    const int lane = tid & 31, wid = tid >> 5;
    const int g = lane >> 2, tid4 = lane & 3;
    const int warpM = wid & 3;
    const int warpN = wid >> 2;
    const int bm = blockIdx.y * BM, bn = blockIdx.x * BN;

    const int arow = tid >> 3, acc8 = tid & 7;
    const __half* Ag = A + (size_t)(bm + arow) * DIM + acc8 * 8;
    const __half* Bg = B + (size_t)(bn + arow) * DIM + acc8 * 8;
    const uint32_t sdA = sbu + arow * ROWB + acc8 * 16;
    const uint32_t sdB = sbu + A_SZ + arow * ROWB + acc8 * 16;

    auto stage = [&](int s, int kt) {
        const uint32_t so = s * STG_SZ;
        const size_t ko = (size_t)kt * BK;
        #pragma unroll
        for (int i = 0; i < 4; i++)
            cp_async16(sdA + so + i * 64 * ROWB, Ag + ko + (size_t)(64 * i) * DIM);
        #pragma unroll
        for (int i = 0; i < 2; i++)
            cp_async16(sdB + so + i * 64 * ROWB, Bg + ko + (size_t)(64 * i) * DIM);
    };

    const uint32_t aoff = (warpM * 64 + (lane & 15)) * ROWB + ((lane >> 4) << 4);
    const uint32_t boff = A_SZ + (warpN * 32 + (lane & 15)) * ROWB + ((lane >> 4) << 4);

    float acc[4][4][4];
    #pragma unroll
    for (int i = 0; i < 4; i++)
        #pragma unroll
        for (int j = 0; j < 4; j++)
            #pragma unroll
            for (int q = 0; q < 4; q++)
                acc[i][j][q] = 0.f;

    stage(0, 0); cp_commit();

    const int NKT = DIM / BK;
    int s = 0;
    for (int kt = 0; kt < NKT; kt++) {
        cp_wait<0>();
        __syncthreads();
        if (kt + 1 < NKT) { stage(s ^ 1, kt + 1); cp_commit(); }

        const uint32_t ab = sbu + s * STG_SZ + aoff;
        const uint32_t bb = sbu + s * STG_SZ + boff;
        #pragma unroll
        for (int ks = 0; ks < 4; ks++) {
            uint32_t af[4][4], bf[2][4];
            #pragma unroll
            for (int mt = 0; mt < 4; mt++)
                ldsm_x4(af[mt], ab + mt * 16 * ROWB + ks * 32);
            #pragma unroll
            for (int p = 0; p < 2; p++)
                ldsm_x4(bf[p], bb + p * 16 * ROWB + ks * 32);
            #pragma unroll
            for (int mt = 0; mt < 4; mt++)
                #pragma unroll
                for (int p = 0; p < 2; p++) {
                    mma_f16_16x8x16(acc[mt][2 * p],
                                    af[mt][0], af[mt][1], af[mt][2], af[mt][3],
                                    bf[p][0], bf[p][2]);
                    mma_f16_16x8x16(acc[mt][2 * p + 1],
                                    af[mt][0], af[mt][1], af[mt][2], af[mt][3],
                                    bf[p][1], bf[p][3]);
                }
        }
        s ^= 1;
    }

    #pragma unroll
    for (int mt = 0; mt < 4; mt++) {
        const int r0 = bm + warpM * 64 + mt * 16 + g;
        #pragma unroll
        for (int j = 0; j < 4; j++) {
            const int ncol = bn + warpN * 32 + (j >> 1) * 16 + (j & 1) * 8;
            const float* a = acc[mt][j];
            *(float2*)(Cout + (size_t)r0 * DIM + ncol + 2 * tid4) =
                make_float2(a[0], a[1]);
            *(float2*)(Cout + (size_t)(r0 + 8) * DIM + ncol + 2 * tid4) =
                make_float2(a[2], a[3]);
        }
    }
}

// ---------------------------------------------------------------------------
// fp32 -> fp16 prepass: z 0..3 = quarters of x, z 4..7 = weights
// ---------------------------------------------------------------------------
__global__ void prep(const float4* __restrict__ x,
                     const float4* __restrict__ w0, const float4* __restrict__ w1,
                     const float4* __restrict__ w2, const float4* __restrict__ w3)
{
    const int z = blockIdx.z;
    const float4* src;
    uint2* dst;
    int n4;
    if (z < 4) {
        const int quarter = NTOK * DIM / 16;
        src = x + (size_t)z * quarter;
        dst = (uint2*)g_xh + (size_t)z * quarter;
        n4 = quarter;
    } else {
        src = (z == 4) ? w0 : (z == 5) ? w1 : (z == 6) ? w2 : w3;
        dst = (uint2*)((z == 4) ? g_wqh : (z == 5) ? g_wkh : (z == 6) ? g_wvh : g_woh);
        n4 = DIM * DIM / 4;
    }
    int i = blockIdx.x * blockDim.x + threadIdx.x;
    const int stride = gridDim.x * blockDim.x;
    for (; i < n4; i += stride) {
        float4 v = src[i];
        __half2 lo = __floats2half2_rn(v.x, v.y);
        __half2 hi = __floats2half2_rn(v.z, v.w);
        dst[i] = make_uint2(*(uint32_t*)&lo, *(uint32_t*)&hi);
    }
}

// ---------------------------------------------------------------------------
extern "C" void kernel_launch(void* const* d_in, const int* in_sizes, int n_in,
                              void* d_out, int out_size)
{
    const float* x    = (const float*)d_in[0];
    const float* rope = (const float*)d_in[1];
    const float* wq   = (const float*)d_in[2];
    const float* wk   = (const float*)d_in[3];
    const float* wv   = (const float*)d_in[4];
    const float* wo   = (const float*)d_in[5];
    float* out        = (float*)d_out;

    cudaFuncSetAttribute(fused_qkv_attn, cudaFuncAttributeMaxDynamicSharedMemorySize, FSMEM);
    cudaFuncSetAttribute(gemm_wo,        cudaFuncAttributeMaxDynamicSharedMemorySize, GSMEM);

    prep<<<dim3(256, 1, 8), 256>>>((const float4*)x, (const float4*)wq,
                                   (const float4*)wk, (const float4*)wv,
                                   (const float4*)wo);

    fused_qkv_attn<<<dim3(DIM / FBN, NTOK / FBM), 512, FSMEM>>>(rope);

    gemm_wo<<<dim3(DIM / BN, NTOK / BM), 512, GSMEM>>>(out);
}